// round 1
// baseline (speedup 1.0000x reference)
#include <cuda_runtime.h>
#include <math.h>

#define Dd 64
#define DM 128
#define DI 256
#define HID 256
#define Bq 128
#define NN 200
#define FEW 5
#define NRELS 500
#define NPQ (Bq*NN)
#define NPS (FEW*NN)
#define NPTOT (2*NPQ + 2*NPS)   // 53200
#define LN_EPS 0.001f

// ---------------- device scratch ----------------
__device__ float g_qsum[Bq*DM];
__device__ float g_ssum[FEW*DM];
__device__ int   g_cnt[512];
__device__ int   g_off[512];
__device__ int   g_pos[512];
__device__ int2  g_pairs[NPTOT];
__device__ float g_query[Bq*DM];
__device__ float g_support[FEW*DM];
__device__ float g_query_g[Bq*DM];
__device__ float g_support_g[FEW*DM];
__device__ float g_xproj[Bq*4*HID];
__device__ float g_gates[Bq*4*HID];
__device__ float g_c[Bq*HID];
__device__ float g_hr[Bq*2*DM];

__device__ __forceinline__ float sigmoidf_(float x) { return 1.0f / (1.0f + expf(-x)); }

// ---------------- K0: zero scratch ----------------
__global__ void zero_kernel() {
    int i = blockIdx.x * blockDim.x + threadIdx.x;
    if (i < Bq*DM) g_qsum[i] = 0.0f;
    if (i < FEW*DM) g_ssum[i] = 0.0f;
    if (i < 512) g_cnt[i] = 0;
}

// decode global pair index -> (rel, ent, dest-slot)
__device__ __forceinline__ int pair_decode(int idx,
        const int* __restrict__ ql, const int* __restrict__ qr,
        const int* __restrict__ sl, const int* __restrict__ sr,
        int& rel, int& ent) {
    if (idx < NPQ) { const int* c = ql + idx*2; rel = c[0]; ent = c[1]; return (idx/NN)*2; }
    idx -= NPQ;
    if (idx < NPQ) { const int* c = qr + idx*2; rel = c[0]; ent = c[1]; return (idx/NN)*2 + 1; }
    idx -= NPQ;
    if (idx < NPS) { const int* c = sl + idx*2; rel = c[0]; ent = c[1]; return 2*Bq + (idx/NN)*2; }
    idx -= NPS;
    { const int* c = sr + idx*2; rel = c[0]; ent = c[1]; return 2*Bq + (idx/NN)*2 + 1; }
}

// ---------------- K1: count pairs per rel ----------------
__global__ void count_kernel(const int* __restrict__ ql, const int* __restrict__ qr,
                             const int* __restrict__ sl, const int* __restrict__ sr) {
    int idx = blockIdx.x * blockDim.x + threadIdx.x;
    if (idx >= NPTOT) return;
    int rel, ent;
    pair_decode(idx, ql, qr, sl, sr, rel, ent);
    atomicAdd(&g_cnt[rel], 1);
}

// ---------------- K2: exclusive scan (500 bins) ----------------
__global__ void scan_kernel() {
    __shared__ int s[512];
    int t = threadIdx.x;
    int c = (t < NRELS) ? g_cnt[t] : 0;
    s[t] = c;
    __syncthreads();
    for (int d = 1; d < 512; d <<= 1) {
        int v = (t >= d) ? s[t-d] : 0;
        __syncthreads();
        s[t] += v;
        __syncthreads();
    }
    if (t < NRELS) { int off = s[t] - c; g_off[t] = off; g_pos[t] = off; }
}

// ---------------- K3: scatter pair records ----------------
__global__ void scatter_kernel(const int* __restrict__ ql, const int* __restrict__ qr,
                               const int* __restrict__ sl, const int* __restrict__ sr) {
    int idx = blockIdx.x * blockDim.x + threadIdx.x;
    if (idx >= NPTOT) return;
    int rel, ent;
    int dest = pair_decode(idx, ql, qr, sl, sr, rel, ent);
    int pos = atomicAdd(&g_pos[rel], 1);
    g_pairs[pos] = make_int2(dest, ent);
}

// ---------------- K4: binned neighbor-encoder core ----------------
// one block per rel; R staged in smem; 8 warps * 4 pairs per group.
__global__ __launch_bounds__(256) void rescal_main(const float* __restrict__ ent_emb,
                                                   const float* __restrict__ rel_mat) {
    __shared__ __align__(16) float sR[64*68];   // pitch 68 -> conflict-free float4 reads
    __shared__ __align__(16) float sE[8][4][64];
    int r = blockIdx.x;
    int t = threadIdx.x;
    const float* R = rel_mat + (size_t)r * 4096;
    for (int i = t; i < 4096; i += 256) sR[(i >> 6) * 68 + (i & 63)] = R[i];
    int cnt = g_cnt[r];
    int off = g_off[r];
    __syncthreads();
    if (cnt == 0) return;
    int w = t >> 5, lane = t & 31;

    for (int base = w * 4; base < cnt; base += 32) {
        int np = min(4, cnt - base);
        int dests[4];
        #pragma unroll
        for (int p = 0; p < 4; p++) {
            if (p < np) {
                int2 pr = g_pairs[off + base + p];
                dests[p] = pr.x;
                const float* e = ent_emb + (size_t)pr.y * 64;
                sE[w][p][lane]      = e[lane];
                sE[w][p][lane + 32] = e[lane + 32];
            }
        }
        __syncwarp();
        float acc0[4] = {0,0,0,0}, acc1[4] = {0,0,0,0};
        #pragma unroll
        for (int j = 0; j < 64; j += 4) {
            float4 r0 = *(const float4*)&sR[lane * 68 + j];
            float4 r1 = *(const float4*)&sR[(lane + 32) * 68 + j];
            #pragma unroll
            for (int p = 0; p < 4; p++) {
                float4 ev = *(const float4*)&sE[w][p][j];
                acc0[p] += r0.x*ev.x + r0.y*ev.y + r0.z*ev.z + r0.w*ev.w;
                acc1[p] += r1.x*ev.x + r1.y*ev.y + r1.z*ev.z + r1.w*ev.w;
            }
        }
        #pragma unroll
        for (int p = 0; p < 4; p++) {
            if (p < np) {
                int d = dests[p];
                float* dst;
                if (d < 2*Bq) dst = g_qsum + (d >> 1) * DM + (d & 1) * Dd;
                else { int s2 = d - 2*Bq; dst = g_ssum + (s2 >> 1) * DM + (s2 & 1) * Dd; }
                atomicAdd(&dst[lane],      acc0[p]);
                atomicAdd(&dst[lane + 32], acc1[p]);
            }
        }
        __syncwarp();
    }
}

// ---------------- K5: gcn finalize (msg_sum @ W + bias, /deg, tanh) ----------------
__global__ void gcn_fin(const float* __restrict__ gcn_w, const float* __restrict__ gcn_wb,
                        const float* __restrict__ gcn_b,
                        const float* __restrict__ qld, const float* __restrict__ qrd,
                        const float* __restrict__ sld, const float* __restrict__ srd) {
    int slot = blockIdx.x;
    int t = threadIdx.x;  // 64 threads
    const float* S; float deg; float* outp;
    if (slot < 2*Bq) {
        int b = slot >> 1, half = slot & 1;
        S = g_qsum + b * DM + half * Dd;
        deg = half ? qrd[b] : qld[b];
        outp = g_query + b * DM + half * Dd;
    } else {
        int s2 = slot - 2*Bq;
        int s = s2 >> 1, half = s2 & 1;
        S = g_ssum + s * DM + half * Dd;
        deg = half ? srd[s] : sld[s];
        outp = g_support + s * DM + half * Dd;
    }
    __shared__ float sS[64];
    sS[t] = S[t];
    __syncthreads();
    float acc = 0.0f;
    #pragma unroll
    for (int i = 0; i < 64; i++) acc += sS[i] * gcn_w[i * 64 + t];
    acc += (float)NN * (gcn_wb[t] + gcn_b[t]);
    outp[t] = tanhf(acc / deg);
}

// ---------------- K6: support encoder (MLP + residual + LayerNorm ddof=1) ----------------
__global__ __launch_bounds__(256) void supp_enc(const float* __restrict__ w1, const float* __restrict__ b1,
                                                const float* __restrict__ w2, const float* __restrict__ b2,
                                                const float* __restrict__ lg, const float* __restrict__ lb) {
    int row = blockIdx.x;   // 0..132
    int t = threadIdx.x;    // 256
    const float* x = (row < Bq) ? (g_query + row * DM) : (g_support + (row - Bq) * DM);
    float* y = (row < Bq) ? (g_query_g + row * DM) : (g_support_g + (row - Bq) * DM);
    __shared__ float sx[DM];
    __shared__ float sa[DI];
    __shared__ float sh[DM];
    __shared__ float sred[64];
    __shared__ float smu, ssig;
    if (t < DM) sx[t] = x[t];
    __syncthreads();
    {
        float a = b1[t];
        #pragma unroll 8
        for (int j = 0; j < DM; j++) a += sx[j] * w1[j * DI + t];
        sa[t] = fmaxf(a, 0.0f);
    }
    __syncthreads();
    if (t < DM) {
        float h = b2[t] + sx[t];
        #pragma unroll 8
        for (int j = 0; j < DI; j++) h += sa[j] * w2[j * DM + t];
        sh[t] = h;
    }
    __syncthreads();
    // mean
    if (t < 64) sred[t] = sh[t] + sh[t + 64];
    __syncthreads();
    if (t < 32) {
        float v = sred[t] + sred[t + 32];
        for (int o = 16; o; o >>= 1) v += __shfl_down_sync(0xffffffff, v, o);
        if (t == 0) smu = v / (float)DM;
    }
    __syncthreads();
    float mu = smu;
    // variance (ddof=1)
    if (t < 64) {
        float d0 = sh[t] - mu, d1 = sh[t + 64] - mu;
        sred[t] = d0 * d0 + d1 * d1;
    }
    __syncthreads();
    if (t < 32) {
        float v = sred[t] + sred[t + 32];
        for (int o = 16; o; o >>= 1) v += __shfl_down_sync(0xffffffff, v, o);
        if (t == 0) ssig = sqrtf(v / (float)(DM - 1));
    }
    __syncthreads();
    if (t < DM) {
        y[t] = (sh[t] - mu) / (ssig + LN_EPS) * lg[t] + lb[t];
    }
}

// ---------------- generic 16x64-tile GEMM: C = A@B (+Cadd) (+bias1+bias2) ----------------
template<int K>
__global__ __launch_bounds__(256) void gemm16x64(const float* __restrict__ A, const float* __restrict__ Bm,
                                                 const float* __restrict__ Cadd,
                                                 const float* __restrict__ b1, const float* __restrict__ b2,
                                                 float* __restrict__ C, int N) {
    __shared__ float sA[16 * K];
    int t = threadIdx.x;
    int row0 = blockIdx.x * 16, col0 = blockIdx.y * 64;
    for (int i = t; i < 16 * K; i += 256) {
        int r = i / K, k = i - r * K;
        sA[i] = A[(row0 + r) * K + k];
    }
    __syncthreads();
    int row = row0 + t / 16;
    int col = col0 + (t % 16) * 4;
    const float* ar = &sA[(t / 16) * K];
    float4 acc = make_float4(0.f, 0.f, 0.f, 0.f);
    #pragma unroll 8
    for (int k = 0; k < K; k++) {
        float4 bv = *(const float4*)&Bm[(size_t)k * N + col];
        float a = ar[k];
        acc.x += a * bv.x; acc.y += a * bv.y; acc.z += a * bv.z; acc.w += a * bv.w;
    }
    if (Cadd) {
        float4 cv = *(const float4*)&Cadd[(size_t)row * N + col];
        acc.x += cv.x; acc.y += cv.y; acc.z += cv.z; acc.w += cv.w;
    }
    if (b1) {
        acc.x += b1[col]   + b2[col];
        acc.y += b1[col+1] + b2[col+1];
        acc.z += b1[col+2] + b2[col+2];
        acc.w += b1[col+3] + b2[col+3];
    }
    *(float4*)&C[(size_t)row * N + col] = acc;
}

// ---------------- K9: LSTM cell elementwise + attention (one block per batch row) ----------------
__global__ __launch_bounds__(256) void lstm_step(const float* __restrict__ gates,
                                                 float* __restrict__ out, int first, int last) {
    int b = blockIdx.x;
    int t = threadIdx.x;
    __shared__ float sh[DM];
    __shared__ float slog[8];
    __shared__ float sattn[8];
    const float* gr = gates + (size_t)b * 1024;
    float gi = gr[t];
    float gf = gr[256 + t];
    float gg = gr[512 + t];
    float go = gr[768 + t];
    float cp = first ? 0.0f : g_c[b * HID + t];
    float cn = sigmoidf_(gf) * cp + sigmoidf_(gi) * tanhf(gg);
    g_c[b * HID + t] = cn;
    if (t < DM) {
        float hro = sigmoidf_(go) * tanhf(cn);
        sh[t] = g_query_g[b * DM + t] + hro;
    }
    __syncthreads();
    int w = t >> 5, lane = t & 31;
    if (w < FEW) {
        const float* sup = g_support_g + w * DM;
        float v = sh[lane] * sup[lane] + sh[lane + 32] * sup[lane + 32]
                + sh[lane + 64] * sup[lane + 64] + sh[lane + 96] * sup[lane + 96];
        for (int o = 16; o; o >>= 1) v += __shfl_down_sync(0xffffffff, v, o);
        if (lane == 0) slog[w] = v;
    }
    __syncthreads();
    if (t == 0) {
        float mx = slog[0];
        #pragma unroll
        for (int j = 1; j < FEW; j++) mx = fmaxf(mx, slog[j]);
        float s = 0.0f;
        float e[FEW];
        #pragma unroll
        for (int j = 0; j < FEW; j++) { e[j] = expf(slog[j] - mx); s += e[j]; }
        #pragma unroll
        for (int j = 0; j < FEW; j++) sattn[j] = e[j] / s;
    }
    __syncthreads();
    if (t < DM) {
        float r = 0.0f;
        #pragma unroll
        for (int j = 0; j < FEW; j++) r += sattn[j] * g_support_g[j * DM + t];
        g_hr[b * (2*DM) + t] = sh[t];
        g_hr[b * (2*DM) + DM + t] = r;
    }
    if (last && t < FEW) out[b * FEW + t] = slog[t];   // final output = h @ support^T (pre-softmax logits)
}

// ---------------- host ----------------
extern "C" void kernel_launch(void* const* d_in, const int* in_sizes, int n_in,
                              void* d_out, int out_size) {
    const int*   ql     = (const int*)d_in[0];
    const int*   qr     = (const int*)d_in[1];
    const int*   sl     = (const int*)d_in[2];
    const int*   sr     = (const int*)d_in[3];
    const float* qld    = (const float*)d_in[4];
    const float* qrd    = (const float*)d_in[5];
    const float* sld    = (const float*)d_in[6];
    const float* srd    = (const float*)d_in[7];
    const float* ent    = (const float*)d_in[8];
    const float* relm   = (const float*)d_in[9];
    const float* gcn_w  = (const float*)d_in[10];
    const float* gcn_wb = (const float*)d_in[11];
    const float* gcn_b  = (const float*)d_in[12];
    const float* se_w1  = (const float*)d_in[13];
    const float* se_b1  = (const float*)d_in[14];
    const float* se_w2  = (const float*)d_in[15];
    const float* se_b2  = (const float*)d_in[16];
    const float* ln_g   = (const float*)d_in[17];
    const float* ln_b   = (const float*)d_in[18];
    const float* wih    = (const float*)d_in[19];
    const float* whh    = (const float*)d_in[20];
    const float* bih    = (const float*)d_in[21];
    const float* bhh    = (const float*)d_in[22];
    float* out = (float*)d_out;

    zero_kernel<<<(Bq*DM + 255) / 256, 256>>>();
    count_kernel<<<(NPTOT + 255) / 256, 256>>>(ql, qr, sl, sr);
    scan_kernel<<<1, 512>>>();
    scatter_kernel<<<(NPTOT + 255) / 256, 256>>>(ql, qr, sl, sr);
    rescal_main<<<NRELS, 256>>>(ent, relm);
    gcn_fin<<<2*Bq + 2*FEW, 64>>>(gcn_w, gcn_wb, gcn_b, qld, qrd, sld, srd);
    supp_enc<<<Bq + FEW, 256>>>(se_w1, se_b1, se_w2, se_b2, ln_g, ln_b);

    // x_proj = query_g @ wih + bih + bhh   (M=128, K=128, N=1024)
    {
        float* xp; cudaGetSymbolAddress((void**)&xp, g_xproj);
        float* qg; cudaGetSymbolAddress((void**)&qg, g_query_g);
        gemm16x64<128><<<dim3(8, 16), 256>>>(qg, wih, nullptr, bih, bhh, xp, 1024);
    }
    float* xp; cudaGetSymbolAddress((void**)&xp, g_xproj);
    float* gt; cudaGetSymbolAddress((void**)&gt, g_gates);
    float* hr; cudaGetSymbolAddress((void**)&hr, g_hr);

    // step 0: h_r = 0 -> gates = x_proj directly
    lstm_step<<<Bq, 256>>>(xp, out, /*first=*/1, /*last=*/0);
    // steps 1..3
    for (int s = 1; s < 4; s++) {
        gemm16x64<256><<<dim3(8, 16), 256>>>(hr, whh, xp, nullptr, nullptr, gt, 1024);
        lstm_step<<<Bq, 256>>>(gt, out, /*first=*/0, /*last=*/(s == 3) ? 1 : 0);
    }
}

// round 2
// speedup vs baseline: 1.0270x; 1.0270x over previous
#include <cuda_runtime.h>
#include <math.h>
#include <stdint.h>

#define Dd 64
#define DM 128
#define DI 256
#define HID 256
#define Bq 128
#define NN 200
#define FEW 5
#define NRELS 500
#define NPQ (Bq*NN)
#define NPS (FEW*NN)
#define NPTOT (2*NPQ + 2*NPS)   // 53200
#define CAP 512
#define LN_EPS 0.001f
#define NBAR 9

// ---------------- device scratch ----------------
__device__ int   g_cnt[512];                 // zero-initialized; self-zeroed by rescal
__device__ int2  g_pairs[NRELS*CAP];         // (orig_idx, ent)
__device__ float g_msg[(size_t)NPTOT*64];    // per-pair matvec results (13.6MB)
__device__ float g_query[Bq*DM];
__device__ float g_support[FEW*DM];
__device__ float g_query_g[Bq*DM];
__device__ float g_support_g[FEW*DM];
__device__ float g_xproj[Bq*4*HID];
__device__ float g_gates[Bq*4*HID];
__device__ float g_c[Bq*HID];
__device__ float g_hr[Bq*2*DM];
__device__ volatile unsigned long long g_barcnt;   // monotonic, never reset

__device__ __forceinline__ float sigmoidf_(float x) { return 1.0f / (1.0f + expf(-x)); }

// packed fp32x2 helpers (Blackwell FFMA2)
#define FPACK2(d, f)      asm("mov.b64 %0, {%1, %1};" : "=l"(d) : "f"(f))
#define FMA2(acc, e, r)   asm("fma.rn.f32x2 %0, %1, %2, %3;" : "=l"(acc) : "l"(e), "l"(r), "l"(acc))
#define UNPACK2(lo, hi, v) asm("mov.b64 {%0, %1}, %2;" : "=f"(lo), "=f"(hi) : "l"(v))

// ---------------- K1: scatter into padded bins ----------------
__global__ __launch_bounds__(256) void scatter_kernel(const int2* __restrict__ ql,
                                                      const int2* __restrict__ qr,
                                                      const int2* __restrict__ sl,
                                                      const int2* __restrict__ sr) {
    int base = (blockIdx.x * 256 + threadIdx.x) * 4;
    #pragma unroll
    for (int u = 0; u < 4; u++) {
        int idx = base + u;
        if (idx >= NPTOT) return;
        int2 c;
        if (idx < NPQ)            c = ql[idx];
        else if (idx < 2*NPQ)     c = qr[idx - NPQ];
        else if (idx < 2*NPQ+NPS) c = sl[idx - 2*NPQ];
        else                      c = sr[idx - 2*NPQ - NPS];
        int rel = c.x;
        int pos = atomicAdd(&g_cnt[rel], 1);
        if (pos < CAP) g_pairs[rel * CAP + pos] = make_int2(idx, c.y);
    }
}

// ---------------- K2: binned RESCAL core (no atomics, FFMA2) ----------------
__global__ __launch_bounds__(256) void rescal_main(const float* __restrict__ ent_emb,
                                                   const float* __restrict__ rel_mat) {
    __shared__ __align__(16) float sR[64*68];     // pitch 68 floats: conflict-free float4
    __shared__ __align__(16) float sE01[8][128];  // packed {e0[j],e1[j]} per j
    __shared__ __align__(16) float sE23[8][128];
    int r = blockIdx.x;
    int t = threadIdx.x;
    int cnt = g_cnt[r];
    __syncthreads();
    if (t == 0) g_cnt[r] = 0;                     // restore invariant for next launch
    if (cnt == 0) return;
    if (cnt > CAP) cnt = CAP;

    const float* R = rel_mat + (size_t)r * 4096;
    for (int i = t; i < 4096; i += 256) sR[(i >> 6) * 68 + (i & 63)] = R[i];
    __syncthreads();

    int w = t >> 5, lane = t & 31;
    float* e01 = &sE01[w][0];
    float* e23 = &sE23[w][0];

    for (int base = w * 4; base < cnt; base += 32) {
        int np = min(4, cnt - base);
        int origs[4];
        #pragma unroll
        for (int p = 0; p < 4; p++) {
            if (p < np) {
                int2 pr = g_pairs[r * CAP + base + p];
                origs[p] = pr.x;
                const float2* e2 = (const float2*)(ent_emb + (size_t)pr.y * 64);
                float2 v = e2[lane];                 // elements 2*lane, 2*lane+1
                float* dstE = (p < 2) ? e01 : e23;
                int pp = p & 1;
                dstE[4*lane + pp]     = v.x;         // j=2lane   slot {j*2+pp}
                dstE[4*lane + 2 + pp] = v.y;         // j=2lane+1
            }
        }
        __syncwarp();
        unsigned long long aA01=0, aA23=0, aB01=0, aB23=0;
        #pragma unroll
        for (int j4 = 0; j4 < 64; j4 += 4) {
            float4 rA = *(const float4*)&sR[lane * 68 + j4];
            float4 rB = *(const float4*)&sR[(lane + 32) * 68 + j4];
            ulonglong2 E01a = *(const ulonglong2*)(e01 + j4*2);     // j4, j4+1
            ulonglong2 E01b = *(const ulonglong2*)(e01 + j4*2 + 4); // j4+2, j4+3
            ulonglong2 E23a = *(const ulonglong2*)(e23 + j4*2);
            ulonglong2 E23b = *(const ulonglong2*)(e23 + j4*2 + 4);
            unsigned long long dA, dB;
            FPACK2(dA, rA.x); FPACK2(dB, rB.x);
            FMA2(aA01, E01a.x, dA); FMA2(aA23, E23a.x, dA);
            FMA2(aB01, E01a.x, dB); FMA2(aB23, E23a.x, dB);
            FPACK2(dA, rA.y); FPACK2(dB, rB.y);
            FMA2(aA01, E01a.y, dA); FMA2(aA23, E23a.y, dA);
            FMA2(aB01, E01a.y, dB); FMA2(aB23, E23a.y, dB);
            FPACK2(dA, rA.z); FPACK2(dB, rB.z);
            FMA2(aA01, E01b.x, dA); FMA2(aA23, E23b.x, dA);
            FMA2(aB01, E01b.x, dB); FMA2(aB23, E23b.x, dB);
            FPACK2(dA, rA.w); FPACK2(dB, rB.w);
            FMA2(aA01, E01b.y, dA); FMA2(aA23, E23b.y, dA);
            FMA2(aB01, E01b.y, dB); FMA2(aB23, E23b.y, dB);
        }
        float accA[4], accB[4];
        UNPACK2(accA[0], accA[1], aA01); UNPACK2(accA[2], accA[3], aA23);
        UNPACK2(accB[0], accB[1], aB01); UNPACK2(accB[2], accB[3], aB23);
        #pragma unroll
        for (int p = 0; p < 4; p++) {
            if (p < np) {
                float* dst = g_msg + (size_t)origs[p] * 64;
                dst[lane]      = accA[p];
                dst[lane + 32] = accB[p];
            }
        }
        __syncwarp();
    }
}

// ---------------- software grid barrier (monotonic epoch counter) ----------------
__device__ __forceinline__ void grid_bar(unsigned long long base, int k) {
    __threadfence();            // release this thread's writes
    __syncthreads();
    if (threadIdx.x == 0) {
        atomicAdd((unsigned long long*)&g_barcnt, 1ULL);
        unsigned long long target = base + 128ULL * (unsigned long long)(k + 1);
        while (g_barcnt < target) __nanosleep(128);
        __threadfence();        // acquire; flushes L1D (CCTL.IVALL)
    }
    __syncthreads();
}

// ---------------- fused 16x64-tile GEMM (N=1024 fixed), FFMA2 ----------------
template<int K>
__device__ __forceinline__ void gemm_tile(const float* __restrict__ A, const float* __restrict__ Bm,
                                          const float* __restrict__ Cadd,
                                          const float* __restrict__ b1, const float* __restrict__ b2,
                                          float* __restrict__ C, float* sA2, int tid, int bid) {
    int row0 = (bid >> 4) * 16, col0 = (bid & 15) * 64;
    for (int i = tid; i < 16 * K; i += 256) {
        int r = i / K, k = i - r * K;
        float a = A[(size_t)(row0 + r) * K + k];
        sA2[2*i] = a; sA2[2*i + 1] = a;       // duplicated for LDS.64 -> packed {a,a}
    }
    __syncthreads();
    int row = row0 + (tid >> 4), col = col0 + (tid & 15) * 4;
    const float* ar = sA2 + (tid >> 4) * (2 * K);
    unsigned long long acc0 = 0ULL, acc1 = 0ULL;
    #pragma unroll 16
    for (int k = 0; k < K; k++) {
        ulonglong2 bv = *(const ulonglong2*)(Bm + (size_t)k * 1024 + col);
        unsigned long long a2 = *(const unsigned long long*)(ar + 2 * k);
        FMA2(acc0, bv.x, a2);
        FMA2(acc1, bv.y, a2);
    }
    float o0, o1, o2, o3;
    UNPACK2(o0, o1, acc0); UNPACK2(o2, o3, acc1);
    if (Cadd) {
        float4 cv = *(const float4*)(Cadd + (size_t)row * 1024 + col);
        o0 += cv.x; o1 += cv.y; o2 += cv.z; o3 += cv.w;
    }
    if (b1) {
        o0 += b1[col]   + b2[col];
        o1 += b1[col+1] + b2[col+1];
        o2 += b1[col+2] + b2[col+2];
        o3 += b1[col+3] + b2[col+3];
    }
    *(float4*)(C + (size_t)row * 1024 + col) = make_float4(o0, o1, o2, o3);
    __syncthreads();
}

// ---------------- support-encoder row (MLP + residual + LN ddof=1) ----------------
__device__ __forceinline__ void supp_row(const float* __restrict__ x, float* __restrict__ y,
        const float* __restrict__ w1, const float* __restrict__ b1,
        const float* __restrict__ w2, const float* __restrict__ b2,
        const float* __restrict__ lg, const float* __restrict__ lb,
        float* sm, int tid) {
    float* sx = sm;            // 128
    float* sa = sm + 128;      // 256
    float* sh = sm + 384;      // 128
    float* sr = sm + 512;      // 64
    float* sc = sm + 576;      // 2 scalars
    if (tid < DM) sx[tid] = x[tid];
    __syncthreads();
    {
        float a = b1[tid];
        #pragma unroll 16
        for (int j = 0; j < DM; j++) a += sx[j] * w1[j * DI + tid];
        sa[tid] = fmaxf(a, 0.0f);
    }
    __syncthreads();
    if (tid < DM) {
        float h = b2[tid] + sx[tid];
        #pragma unroll 16
        for (int j = 0; j < DI; j++) h += sa[j] * w2[j * DM + tid];
        sh[tid] = h;
    }
    __syncthreads();
    if (tid < 64) sr[tid] = sh[tid] + sh[tid + 64];
    __syncthreads();
    if (tid < 32) {
        float v = sr[tid] + sr[tid + 32];
        for (int o = 16; o; o >>= 1) v += __shfl_down_sync(0xffffffff, v, o);
        if (tid == 0) sc[0] = v / (float)DM;
    }
    __syncthreads();
    float mu = sc[0];
    if (tid < 64) {
        float d0 = sh[tid] - mu, d1 = sh[tid + 64] - mu;
        sr[tid] = d0 * d0 + d1 * d1;
    }
    __syncthreads();
    if (tid < 32) {
        float v = sr[tid] + sr[tid + 32];
        for (int o = 16; o; o >>= 1) v += __shfl_down_sync(0xffffffff, v, o);
        if (tid == 0) sc[1] = sqrtf(v / (float)(DM - 1));
    }
    __syncthreads();
    if (tid < DM) y[tid] = (sh[tid] - mu) / (sc[1] + LN_EPS) * lg[tid] + lb[tid];
    __syncthreads();
}

// ---------------- LSTM element step + attention (row = block) ----------------
__device__ __forceinline__ void lstm_elt(const float* __restrict__ gates, float* __restrict__ out,
                                         int first, int last, int b, int tid,
                                         float* sh, float* slog, float* sattn) {
    const float* gr = gates + (size_t)b * 1024;
    float gi = gr[tid], gf = gr[256 + tid], gg = gr[512 + tid], go = gr[768 + tid];
    float cp = first ? 0.0f : g_c[b * HID + tid];
    float cn = sigmoidf_(gf) * cp + sigmoidf_(gi) * tanhf(gg);
    g_c[b * HID + tid] = cn;
    if (tid < DM) sh[tid] = g_query_g[b * DM + tid] + sigmoidf_(go) * tanhf(cn);
    __syncthreads();
    int w = tid >> 5, lane = tid & 31;
    if (w < FEW) {
        const float* sup = g_support_g + w * DM;
        float v = sh[lane] * sup[lane] + sh[lane+32] * sup[lane+32]
                + sh[lane+64] * sup[lane+64] + sh[lane+96] * sup[lane+96];
        for (int o = 16; o; o >>= 1) v += __shfl_down_sync(0xffffffff, v, o);
        if (lane == 0) slog[w] = v;
    }
    __syncthreads();
    if (last) {
        if (tid < FEW) out[b * FEW + tid] = slog[tid];
        return;
    }
    if (tid == 0) {
        float mx = slog[0];
        #pragma unroll
        for (int j = 1; j < FEW; j++) mx = fmaxf(mx, slog[j]);
        float s = 0.0f, e[FEW];
        #pragma unroll
        for (int j = 0; j < FEW; j++) { e[j] = expf(slog[j] - mx); s += e[j]; }
        #pragma unroll
        for (int j = 0; j < FEW; j++) sattn[j] = e[j] / s;
    }
    __syncthreads();
    if (tid < DM) {
        float rr = 0.0f;
        #pragma unroll
        for (int j = 0; j < FEW; j++) rr += sattn[j] * g_support_g[j * DM + tid];
        g_hr[b * (2*DM) + tid]      = sh[tid];
        g_hr[b * (2*DM) + DM + tid] = rr;
    }
    __syncthreads();
}

// ---------------- K3: one-wave mega kernel ----------------
__global__ __launch_bounds__(256) void mega_kernel(
        const float* __restrict__ qld, const float* __restrict__ qrd,
        const float* __restrict__ sld, const float* __restrict__ srd,
        const float* __restrict__ gcn_w, const float* __restrict__ gcn_wb, const float* __restrict__ gcn_b,
        const float* __restrict__ w1, const float* __restrict__ b1,
        const float* __restrict__ w2, const float* __restrict__ b2,
        const float* __restrict__ lg, const float* __restrict__ lb,
        const float* __restrict__ wih, const float* __restrict__ whh,
        const float* __restrict__ bih, const float* __restrict__ bhh,
        float* __restrict__ out) {
    __shared__ __align__(16) float sbuf[8192];   // 32KB: GEMM sA2 (16x256 dup) / supp / reduce
    __shared__ float sh2[DM];
    __shared__ float sred2[64];
    __shared__ float slog[8];
    __shared__ float sattn[8];
    __shared__ unsigned long long s_base;
    int tid = threadIdx.x, bid = blockIdx.x;
    if (tid == 0) {
        unsigned long long c = g_barcnt;
        s_base = (c / (128ULL * NBAR)) * (128ULL * NBAR);
    }
    __syncthreads();
    unsigned long long bbase = s_base;

    // ---- Stage A: msg reduction + gcn finalize ----
    for (int dd = bid; dd < 2*Bq + 2*FEW; dd += 128) {
        int base; float deg; float* outp;
        if (dd < 2*Bq) {
            int b = dd >> 1, half = dd & 1;
            base = (half ? NPQ : 0) + b * NN;
            deg = half ? qrd[b] : qld[b];
            outp = g_query + b * DM + half * Dd;
        } else {
            int s2 = dd - 2*Bq; int s = s2 >> 1, half = s2 & 1;
            base = 2*NPQ + (half ? NPS : 0) + s * NN;
            deg = half ? srd[s] : sld[s];
            outp = g_support + s * DM + half * Dd;
        }
        int c = tid & 63, rg = tid >> 6;
        float part = 0.0f;
        #pragma unroll 10
        for (int j = rg; j < NN; j += 4) part += g_msg[(size_t)(base + j) * 64 + c];
        sbuf[tid] = part;
        __syncthreads();
        if (tid < 64) sred2[tid] = sbuf[tid] + sbuf[tid+64] + sbuf[tid+128] + sbuf[tid+192];
        __syncthreads();
        if (tid < 64) {
            float acc = 0.0f;
            #pragma unroll 16
            for (int i = 0; i < 64; i++) acc += sred2[i] * gcn_w[i * 64 + tid];
            acc += (float)NN * (gcn_wb[tid] + gcn_b[tid]);
            outp[tid] = tanhf(acc / deg);
        }
        __syncthreads();
    }
    grid_bar(bbase, 0);

    // ---- Stage B: support encoder (133 rows) ----
    supp_row(g_query + bid * DM, g_query_g + bid * DM, w1, b1, w2, b2, lg, lb, sbuf, tid);
    if (bid < FEW)
        supp_row(g_support + bid * DM, g_support_g + bid * DM, w1, b1, w2, b2, lg, lb, sbuf, tid);
    grid_bar(bbase, 1);

    // ---- Stage C: x_proj = query_g @ wih + bih + bhh ----
    gemm_tile<128>(g_query_g, wih, nullptr, bih, bhh, g_xproj, sbuf, tid, bid);
    grid_bar(bbase, 2);

    // ---- LSTM step 0 (h_r = 0 -> gates = x_proj) ----
    lstm_elt(g_xproj, out, 1, 0, bid, tid, sh2, slog, sattn);
    grid_bar(bbase, 3);

    // ---- LSTM steps 1..3 ----
    #pragma unroll
    for (int s = 1; s < 4; s++) {
        gemm_tile<256>(g_hr, whh, g_xproj, nullptr, nullptr, g_gates, sbuf, tid, bid);
        grid_bar(bbase, 2 * s + 2);
        lstm_elt(g_gates, out, 0, (s == 3) ? 1 : 0, bid, tid, sh2, slog, sattn);
        if (s < 3) grid_bar(bbase, 2 * s + 3);
    }
}

// ---------------- host ----------------
extern "C" void kernel_launch(void* const* d_in, const int* in_sizes, int n_in,
                              void* d_out, int out_size) {
    const int2*  ql     = (const int2*)d_in[0];
    const int2*  qr     = (const int2*)d_in[1];
    const int2*  sl     = (const int2*)d_in[2];
    const int2*  sr     = (const int2*)d_in[3];
    const float* qld    = (const float*)d_in[4];
    const float* qrd    = (const float*)d_in[5];
    const float* sld    = (const float*)d_in[6];
    const float* srd    = (const float*)d_in[7];
    const float* ent    = (const float*)d_in[8];
    const float* relm   = (const float*)d_in[9];
    const float* gcn_w  = (const float*)d_in[10];
    const float* gcn_wb = (const float*)d_in[11];
    const float* gcn_b  = (const float*)d_in[12];
    const float* se_w1  = (const float*)d_in[13];
    const float* se_b1  = (const float*)d_in[14];
    const float* se_w2  = (const float*)d_in[15];
    const float* se_b2  = (const float*)d_in[16];
    const float* ln_g   = (const float*)d_in[17];
    const float* ln_b   = (const float*)d_in[18];
    const float* wih    = (const float*)d_in[19];
    const float* whh    = (const float*)d_in[20];
    const float* bih    = (const float*)d_in[21];
    const float* bhh    = (const float*)d_in[22];
    float* out = (float*)d_out;

    scatter_kernel<<<(NPTOT/4 + 255) / 256, 256>>>(ql, qr, sl, sr);
    rescal_main<<<NRELS, 256>>>(ent, relm);
    mega_kernel<<<128, 256>>>(qld, qrd, sld, srd, gcn_w, gcn_wb, gcn_b,
                              se_w1, se_b1, se_w2, se_b2, ln_g, ln_b,
                              wih, whh, bih, bhh, out);
}

// round 3
// speedup vs baseline: 1.2961x; 1.2620x over previous
#include <cuda_runtime.h>
#include <math.h>
#include <stdint.h>

#define Dd 64
#define DM 128
#define DI 256
#define HID 256
#define Bq 128
#define NN 200
#define FEW 5
#define NRELS 500
#define NPQ (Bq*NN)
#define NPS (FEW*NN)
#define NPTOT (2*NPQ + 2*NPS)   // 53200
#define CAP 512
#define LN_EPS 0.001f
#define NBAR 10
#define GRID 128

// ---------------- device scratch ----------------
__device__ int   g_cnt[512];                 // zero-init; self-zeroed each pass
__device__ int2  g_pairs[NRELS*CAP];         // (orig_idx, ent)
__device__ float g_msg[(size_t)NPTOT*64];    // per-pair matvec results
__device__ float g_query_g[Bq*DM];
__device__ float g_support_g[FEW*DM];
__device__ float g_xproj[Bq*4*HID];
__device__ float g_gates[Bq*4*HID];
__device__ float g_c[Bq*HID];
__device__ float g_hr[Bq*2*DM];
__device__ unsigned long long g_barcnt;      // monotonic, never reset

__device__ __forceinline__ float sigmoidf_(float x) { return 1.0f / (1.0f + expf(-x)); }

// packed fp32x2 helpers (Blackwell FFMA2)
#define FPACK2(d, f)      asm("mov.b64 %0, {%1, %1};" : "=l"(d) : "f"(f))
#define FMA2(acc, e, r)   asm("fma.rn.f32x2 %0, %1, %2, %3;" : "=l"(acc) : "l"(e), "l"(r), "l"(acc))
#define UNPACK2(lo, hi, v) asm("mov.b64 {%0, %1}, %2;" : "=f"(lo), "=f"(hi) : "l"(v))

// ---------------- grid barrier: monotonic epoch counter, tight acquire spin ----------------
__device__ __forceinline__ void grid_bar(unsigned long long base, int k) {
    __syncthreads();
    if (threadIdx.x == 0) {
        __threadfence();   // release my writes
        atomicAdd(&g_barcnt, 1ULL);
        unsigned long long target = base + (unsigned long long)GRID * (unsigned long long)(k + 1);
        unsigned long long v;
        do {
            asm volatile("ld.global.acquire.gpu.u64 %0, [%1];" : "=l"(v) : "l"(&g_barcnt) : "memory");
        } while (v < target);
        __threadfence();   // CCTL.IVALL: invalidate this SM's L1 for all warps
    }
    __syncthreads();
}

// ---------------- gcn row: reduce 200 msgs per half, matvec, tanh -> smem x[128] ----------------
__device__ __forceinline__ void gcn_row(int baseL, int baseR, float degL, float degR,
        const float* __restrict__ gcn_w, const float* __restrict__ gcn_wb, const float* __restrict__ gcn_b,
        float* sm, int t) {
    float* sp = sm;          // 256
    float* msum = sm + 256;  // 128
    float* x = sm + 384;     // 128 (output)
    {
        int h = t >> 7, rg = (t >> 6) & 1, c = t & 63;
        int base = h ? baseR : baseL;
        float part = 0.0f;
        #pragma unroll 10
        for (int j = rg; j < NN; j += 2) part += g_msg[(size_t)(base + j) * 64 + c];
        sp[t] = part;
    }
    __syncthreads();
    if (t < 128) msum[t] = sp[(t >> 6) * 128 + (t & 63)] + sp[(t >> 6) * 128 + 64 + (t & 63)];
    __syncthreads();
    if (t < 128) {
        int hh = t >> 6, o = t & 63;
        float acc = 0.0f;
        #pragma unroll 16
        for (int i = 0; i < 64; i++) acc += msum[hh * 64 + i] * gcn_w[i * 64 + o];
        acc += (float)NN * (gcn_wb[o] + gcn_b[o]);
        x[t] = tanhf(acc / (hh ? degR : degL));
    }
    __syncthreads();
}

// ---------------- support encoder row: x(smem) -> y(global), MLP+residual+LN(ddof=1) ----------------
__device__ __forceinline__ void supp_row(float* __restrict__ y,
        const float* __restrict__ w1, const float* __restrict__ b1,
        const float* __restrict__ w2, const float* __restrict__ b2,
        const float* __restrict__ lg, const float* __restrict__ lb,
        float* sm, int t) {
    float* x  = sm + 384;    // input (from gcn_row)
    float* sa = sm + 512;    // 256
    float* sh = sm + 768;    // 128
    float* sr = sm + 896;    // 64
    float* sc = sm + 960;    // 2
    {
        float a = b1[t];
        #pragma unroll 32
        for (int j = 0; j < DM; j++) a += x[j] * w1[j * DI + t];
        sa[t] = fmaxf(a, 0.0f);
    }
    __syncthreads();
    if (t < DM) {
        float h = b2[t] + x[t];
        #pragma unroll 32
        for (int j = 0; j < DI; j++) h += sa[j] * w2[j * DM + t];
        sh[t] = h;
    }
    __syncthreads();
    if (t < 64) sr[t] = sh[t] + sh[t + 64];
    __syncthreads();
    if (t < 32) {
        float v = sr[t] + sr[t + 32];
        for (int o = 16; o; o >>= 1) v += __shfl_down_sync(0xffffffff, v, o);
        if (t == 0) sc[0] = v / (float)DM;
    }
    __syncthreads();
    float mu = sc[0];
    if (t < 64) {
        float d0 = sh[t] - mu, d1 = sh[t + 64] - mu;
        sr[t] = d0 * d0 + d1 * d1;
    }
    __syncthreads();
    if (t < 32) {
        float v = sr[t] + sr[t + 32];
        for (int o = 16; o; o >>= 1) v += __shfl_down_sync(0xffffffff, v, o);
        if (t == 0) sc[1] = sqrtf(v / (float)(DM - 1));
    }
    __syncthreads();
    if (t < DM) y[t] = (sh[t] - mu) / (sc[1] + LN_EPS) * lg[t] + lb[t];
    __syncthreads();
}

// ---------------- 64x16-tile GEMM, N=1024: C = A@B (+Cadd) (+b1+b2) ----------------
// block covers 64 rows x 16 cols; per-warp B read = one 64B broadcast slice (1 wavefront).
template<int K, bool ADDC, bool BIAS>
__device__ __forceinline__ void gemm64x16(const float* __restrict__ A, const float* __restrict__ Bm,
        const float* __restrict__ Cadd, const float* __restrict__ b1, const float* __restrict__ b2,
        float* __restrict__ C, float* sAT, int t, int bid) {
    int row0 = (bid >> 6) * 64;
    int col  = (bid & 63) * 16 + (t & 3) * 4;
    int rl   = t >> 2;                       // local row 0..63
    int row  = row0 + rl;
    unsigned long long acc0 = 0ULL, acc1 = 0ULL;
    for (int kc = 0; kc < K; kc += 64) {
        // stage 64x64 A chunk transposed into smem (pitch 65)
        for (int i = t; i < 64 * 16; i += 256) {
            int rr = i >> 4, kq = (i & 15) * 4;
            float4 v = *(const float4*)&A[(size_t)(row0 + rr) * K + kc + kq];
            sAT[(kq + 0) * 65 + rr] = v.x;
            sAT[(kq + 1) * 65 + rr] = v.y;
            sAT[(kq + 2) * 65 + rr] = v.z;
            sAT[(kq + 3) * 65 + rr] = v.w;
        }
        __syncthreads();
        #pragma unroll 16
        for (int k = 0; k < 64; k++) {
            ulonglong2 bv = *(const ulonglong2*)&Bm[(size_t)(kc + k) * 1024 + col];
            unsigned long long a2;
            FPACK2(a2, sAT[k * 65 + rl]);
            FMA2(acc0, bv.x, a2);
            FMA2(acc1, bv.y, a2);
        }
        __syncthreads();
    }
    float o0, o1, o2, o3;
    UNPACK2(o0, o1, acc0); UNPACK2(o2, o3, acc1);
    if (ADDC) {
        float4 cv = *(const float4*)&Cadd[(size_t)row * 1024 + col];
        o0 += cv.x; o1 += cv.y; o2 += cv.z; o3 += cv.w;
    }
    if (BIAS) {
        o0 += b1[col]   + b2[col];
        o1 += b1[col+1] + b2[col+1];
        o2 += b1[col+2] + b2[col+2];
        o3 += b1[col+3] + b2[col+3];
    }
    *(float4*)&C[(size_t)row * 1024 + col] = make_float4(o0, o1, o2, o3);
}

// ---------------- LSTM elementwise + attention (block = batch row) ----------------
__device__ __forceinline__ void lstm_elt(const float* __restrict__ gates, float* __restrict__ out,
                                         int first, int last, int b, int t, float* sm) {
    float* sh = sm;          // 128
    float* slog = sm + 128;  // 8
    float* sattn = sm + 136; // 8
    const float* gr = gates + (size_t)b * 1024;
    float gi = gr[t], gf = gr[256 + t], gg = gr[512 + t], go = gr[768 + t];
    float cp = first ? 0.0f : g_c[b * HID + t];
    float cn = sigmoidf_(gf) * cp + sigmoidf_(gi) * tanhf(gg);
    g_c[b * HID + t] = cn;
    if (t < DM) sh[t] = g_query_g[b * DM + t] + sigmoidf_(go) * tanhf(cn);
    __syncthreads();
    int w = t >> 5, lane = t & 31;
    if (w < FEW) {
        const float* sup = g_support_g + w * DM;
        float v = sh[lane] * sup[lane] + sh[lane+32] * sup[lane+32]
                + sh[lane+64] * sup[lane+64] + sh[lane+96] * sup[lane+96];
        for (int o = 16; o; o >>= 1) v += __shfl_down_sync(0xffffffff, v, o);
        if (lane == 0) slog[w] = v;
    }
    __syncthreads();
    if (last) {
        if (t < FEW) out[b * FEW + t] = slog[t];
        return;
    }
    if (t == 0) {
        float mx = slog[0];
        #pragma unroll
        for (int j = 1; j < FEW; j++) mx = fmaxf(mx, slog[j]);
        float s = 0.0f, e[FEW];
        #pragma unroll
        for (int j = 0; j < FEW; j++) { e[j] = expf(slog[j] - mx); s += e[j]; }
        #pragma unroll
        for (int j = 0; j < FEW; j++) sattn[j] = e[j] / s;
    }
    __syncthreads();
    if (t < DM) {
        float rr = 0.0f;
        #pragma unroll
        for (int j = 0; j < FEW; j++) rr += sattn[j] * g_support_g[j * DM + t];
        g_hr[b * (2*DM) + t]      = sh[t];
        g_hr[b * (2*DM) + DM + t] = rr;
    }
    __syncthreads();
}

// ---------------- THE kernel ----------------
__global__ __launch_bounds__(256, 1) void mega_kernel(
        const int2* __restrict__ ql, const int2* __restrict__ qr,
        const int2* __restrict__ sl, const int2* __restrict__ sr,
        const float* __restrict__ qld, const float* __restrict__ qrd,
        const float* __restrict__ sld, const float* __restrict__ srd,
        const float* __restrict__ ent_emb, const float* __restrict__ rel_mat,
        const float* __restrict__ gcn_w, const float* __restrict__ gcn_wb, const float* __restrict__ gcn_b,
        const float* __restrict__ w1, const float* __restrict__ b1,
        const float* __restrict__ w2, const float* __restrict__ b2,
        const float* __restrict__ lg, const float* __restrict__ lb,
        const float* __restrict__ wih, const float* __restrict__ whh,
        const float* __restrict__ bih, const float* __restrict__ bhh,
        float* __restrict__ out) {
    __shared__ __align__(16) float smem[6656];   // 26KB union
    __shared__ unsigned long long s_base;
    int t = threadIdx.x, bid = blockIdx.x;
    if (t == 0) {
        unsigned long long c;
        asm volatile("ld.global.acquire.gpu.u64 %0, [%1];" : "=l"(c) : "l"(&g_barcnt) : "memory");
        s_base = (c / (unsigned long long)(GRID * NBAR)) * (unsigned long long)(GRID * NBAR);
    }
    __syncthreads();
    unsigned long long bbase = s_base;

    // ===== Stage 0: scatter into padded per-rel bins =====
    {
        int lo = bid * 416, hi = min(lo + 416, NPTOT);
        for (int idx = lo + t; idx < hi; idx += 256) {
            int2 c;
            if (idx < NPQ)                 c = ql[idx];
            else if (idx < 2*NPQ)          c = qr[idx - NPQ];
            else if (idx < 2*NPQ + NPS)    c = sl[idx - 2*NPQ];
            else                           c = sr[idx - 2*NPQ - NPS];
            int pos = atomicAdd(&g_cnt[c.x], 1);
            if (pos < CAP) g_pairs[c.x * CAP + pos] = make_int2(idx, c.y);
        }
    }
    grid_bar(bbase, 0);

    // ===== Stage 1: binned RESCAL matvecs (FFMA2, no atomics) =====
    {
        float* sR   = smem;                 // 64*68 = 4352
        float* sE01 = smem + 4352;          // 8*128
        float* sE23 = smem + 5376;          // 8*128
        int w = t >> 5, lane = t & 31;
        for (int r = bid; r < NRELS; r += GRID) {
            int cnt = g_cnt[r];
            __syncthreads();                // everyone read cnt; prior rel's compute done
            if (t == 0) g_cnt[r] = 0;       // restore invariant for next replay
            if (cnt == 0) continue;
            if (cnt > CAP) cnt = CAP;
            const float* R = rel_mat + (size_t)r * 4096;
            for (int i = t; i < 4096; i += 256) sR[(i >> 6) * 68 + (i & 63)] = R[i];
            __syncthreads();
            float* e01 = sE01 + w * 128;
            float* e23 = sE23 + w * 128;
            for (int base = w * 4; base < cnt; base += 32) {
                int np = min(4, cnt - base);
                int origs[4];
                #pragma unroll
                for (int p = 0; p < 4; p++) {
                    if (p < np) {
                        int2 pr = g_pairs[r * CAP + base + p];
                        origs[p] = pr.x;
                        float2 v = ((const float2*)(ent_emb + (size_t)pr.y * 64))[lane];
                        float* dstE = (p < 2) ? e01 : e23;
                        int pp = p & 1;
                        dstE[4*lane + pp]     = v.x;
                        dstE[4*lane + 2 + pp] = v.y;
                    }
                }
                __syncwarp();
                unsigned long long aA01=0, aA23=0, aB01=0, aB23=0;
                #pragma unroll
                for (int j4 = 0; j4 < 64; j4 += 4) {
                    float4 rA = *(const float4*)&sR[lane * 68 + j4];
                    float4 rB = *(const float4*)&sR[(lane + 32) * 68 + j4];
                    ulonglong2 E01a = *(const ulonglong2*)(e01 + j4*2);
                    ulonglong2 E01b = *(const ulonglong2*)(e01 + j4*2 + 4);
                    ulonglong2 E23a = *(const ulonglong2*)(e23 + j4*2);
                    ulonglong2 E23b = *(const ulonglong2*)(e23 + j4*2 + 4);
                    unsigned long long dA, dB;
                    FPACK2(dA, rA.x); FPACK2(dB, rB.x);
                    FMA2(aA01, E01a.x, dA); FMA2(aA23, E23a.x, dA);
                    FMA2(aB01, E01a.x, dB); FMA2(aB23, E23a.x, dB);
                    FPACK2(dA, rA.y); FPACK2(dB, rB.y);
                    FMA2(aA01, E01a.y, dA); FMA2(aA23, E23a.y, dA);
                    FMA2(aB01, E01a.y, dB); FMA2(aB23, E23a.y, dB);
                    FPACK2(dA, rA.z); FPACK2(dB, rB.z);
                    FMA2(aA01, E01b.x, dA); FMA2(aA23, E23b.x, dA);
                    FMA2(aB01, E01b.x, dB); FMA2(aB23, E23b.x, dB);
                    FPACK2(dA, rA.w); FPACK2(dB, rB.w);
                    FMA2(aA01, E01b.y, dA); FMA2(aA23, E23b.y, dA);
                    FMA2(aB01, E01b.y, dB); FMA2(aB23, E23b.y, dB);
                }
                float accA[4], accB[4];
                UNPACK2(accA[0], accA[1], aA01); UNPACK2(accA[2], accA[3], aA23);
                UNPACK2(accB[0], accB[1], aB01); UNPACK2(accB[2], accB[3], aB23);
                #pragma unroll
                for (int p = 0; p < 4; p++) {
                    if (p < np) {
                        float* dst = g_msg + (size_t)origs[p] * 64;
                        dst[lane]      = accA[p];
                        dst[lane + 32] = accB[p];
                    }
                }
                __syncwarp();
            }
        }
    }
    grid_bar(bbase, 1);

    // ===== Stage 2: gcn finalize + support encoder, fused per row =====
    {
        int q = bid;   // query row
        gcn_row(q * NN, NPQ + q * NN, qld[q], qrd[q], gcn_w, gcn_wb, gcn_b, smem, t);
        supp_row(g_query_g + q * DM, w1, b1, w2, b2, lg, lb, smem, t);
        if (bid < FEW) {
            int s = bid;
            gcn_row(2*NPQ + s * NN, 2*NPQ + NPS + s * NN, sld[s], srd[s],
                    gcn_w, gcn_wb, gcn_b, smem, t);
            supp_row(g_support_g + s * DM, w1, b1, w2, b2, lg, lb, smem, t);
        }
    }
    grid_bar(bbase, 2);

    // ===== Stage 3: x_proj = query_g @ wih + bih + bhh =====
    gemm64x16<128, false, true>(g_query_g, wih, nullptr, bih, bhh, g_xproj, smem, t, bid);
    grid_bar(bbase, 3);

    // ===== Stage 4: LSTM step 0 (h_r = 0 -> gates = x_proj) =====
    lstm_elt(g_xproj, out, 1, 0, bid, t, smem);
    grid_bar(bbase, 4);

    // ===== Stages 5..10: LSTM steps 1..3 =====
    #pragma unroll
    for (int s = 1; s < 4; s++) {
        gemm64x16<256, true, false>(g_hr, whh, g_xproj, nullptr, nullptr, g_gates, smem, t, bid);
        grid_bar(bbase, 2 * s + 3);
        lstm_elt(g_gates, out, 0, (s == 3) ? 1 : 0, bid, t, smem);
        if (s < 3) grid_bar(bbase, 2 * s + 4);
    }
}

// ---------------- host ----------------
extern "C" void kernel_launch(void* const* d_in, const int* in_sizes, int n_in,
                              void* d_out, int out_size) {
    const int2*  ql     = (const int2*)d_in[0];
    const int2*  qr     = (const int2*)d_in[1];
    const int2*  sl     = (const int2*)d_in[2];
    const int2*  sr     = (const int2*)d_in[3];
    const float* qld    = (const float*)d_in[4];
    const float* qrd    = (const float*)d_in[5];
    const float* sld    = (const float*)d_in[6];
    const float* srd    = (const float*)d_in[7];
    const float* ent    = (const float*)d_in[8];
    const float* relm   = (const float*)d_in[9];
    const float* gcn_w  = (const float*)d_in[10];
    const float* gcn_wb = (const float*)d_in[11];
    const float* gcn_b  = (const float*)d_in[12];
    const float* se_w1  = (const float*)d_in[13];
    const float* se_b1  = (const float*)d_in[14];
    const float* se_w2  = (const float*)d_in[15];
    const float* se_b2  = (const float*)d_in[16];
    const float* ln_g   = (const float*)d_in[17];
    const float* ln_b   = (const float*)d_in[18];
    const float* wih    = (const float*)d_in[19];
    const float* whh    = (const float*)d_in[20];
    const float* bih    = (const float*)d_in[21];
    const float* bhh    = (const float*)d_in[22];
    float* out = (float*)d_out;

    mega_kernel<<<GRID, 256>>>(ql, qr, sl, sr, qld, qrd, sld, srd, ent, relm,
                               gcn_w, gcn_wb, gcn_b, se_w1, se_b1, se_w2, se_b2,
                               ln_g, ln_b, wih, whh, bih, bhh, out);
}

// round 4
// speedup vs baseline: 1.8443x; 1.4229x over previous
#include <cuda_runtime.h>
#include <math.h>
#include <stdint.h>

#define Dd 64
#define DM 128
#define DI 256
#define HID 256
#define Bq 128
#define NN 200
#define FEW 5
#define NRELS 500
#define NPQ (Bq*NN)
#define NPS (FEW*NN)
#define NPTOT (2*NPQ + 2*NPS)   // 53200
#define CAP 512
#define LN_EPS 0.001f
#define NBAR 10
#define GRID 144
#define NT 512

// ---------------- device scratch ----------------
__device__ int   g_cnt[512];                 // zero-init; self-zeroed each pass
__device__ int2  g_pairs[NRELS*CAP];
__device__ float g_msg[(size_t)NPTOT*64];
__device__ float g_query_g[Bq*DM];
__device__ float g_support_g[FEW*DM];
__device__ float g_xproj[Bq*4*HID];
__device__ float g_gates[Bq*4*HID];
__device__ float g_c[Bq*HID];
__device__ float g_h[Bq*DM];
__device__ float g_attn[Bq*8];
__device__ float g_SW[FEW*1024];             // support_g @ whh[128:256,:]
__device__ unsigned long long g_barcnt;      // monotonic, never reset

__device__ __forceinline__ float sigmoidf_(float x) { return 1.0f / (1.0f + expf(-x)); }

// packed fp32x2 helpers (Blackwell FFMA2)
#define FPACK2(d, f)      asm("mov.b64 %0, {%1, %1};" : "=l"(d) : "f"(f))
#define FMA2(acc, e, r)   asm("fma.rn.f32x2 %0, %1, %2, %3;" : "=l"(acc) : "l"(e), "l"(r), "l"(acc))
#define UNPACK2(lo, hi, v) asm("mov.b64 {%0, %1}, %2;" : "=f"(lo), "=f"(hi) : "l"(v))

// ---------------- grid barrier: monotonic epoch counter ----------------
__device__ __forceinline__ void grid_bar(unsigned long long base, int k) {
    __syncthreads();
    if (threadIdx.x == 0) {
        __threadfence();
        atomicAdd(&g_barcnt, 1ULL);
        unsigned long long target = base + (unsigned long long)GRID * (unsigned long long)(k + 1);
        unsigned long long v;
        do {
            asm volatile("ld.global.acquire.gpu.u64 %0, [%1];" : "=l"(v) : "l"(&g_barcnt) : "memory");
        } while (v < target);
        __threadfence();
    }
    __syncthreads();
}

// ---------------- gcn row (512 threads): reduce 200 msgs per half, matvec, tanh -> sm x[128]
__device__ __forceinline__ void gcn_row(int baseL, int baseR, float degL, float degR,
        const float* __restrict__ gcn_w, const float* __restrict__ gcn_wb, const float* __restrict__ gcn_b,
        float* sm, int t) {
    float* sp   = sm;          // 512
    float* msum = sm + 512;    // 128
    float* x    = sm + 640;    // 128
    {
        int h = t >> 8, rem = t & 255, rg = rem >> 6, c = rem & 63;
        int base = h ? baseR : baseL;
        float part = 0.0f;
        #pragma unroll 10
        for (int j = rg; j < NN; j += 4) part += g_msg[(size_t)(base + j) * 64 + c];
        sp[t] = part;
    }
    __syncthreads();
    if (t < 128) {
        int b0 = (t >> 6) * 256, o = t & 63;
        msum[t] = sp[b0 + o] + sp[b0 + 64 + o] + sp[b0 + 128 + o] + sp[b0 + 192 + o];
    }
    __syncthreads();
    if (t < 128) {
        int hh = t >> 6, o = t & 63;
        float acc = 0.0f;
        #pragma unroll 16
        for (int i = 0; i < 64; i++) acc += msum[hh * 64 + i] * gcn_w[i * 64 + o];
        acc += (float)NN * (gcn_wb[o] + gcn_b[o]);
        x[t] = tanhf(acc / (hh ? degR : degL));
    }
    __syncthreads();
}

// ---------------- support encoder row: x(sm+640) -> y(global)
__device__ __forceinline__ void supp_row(float* __restrict__ y,
        const float* __restrict__ w1, const float* __restrict__ b1,
        const float* __restrict__ w2, const float* __restrict__ b2,
        const float* __restrict__ lg, const float* __restrict__ lb,
        float* sm, int t) {
    float* x  = sm + 640;    // 128
    float* sa = sm + 768;    // 256
    float* sh = sm + 1024;   // 128
    float* sr = sm + 1152;   // 64
    float* sc = sm + 1216;   // 2
    if (t < DI) {
        float a = b1[t];
        #pragma unroll 16
        for (int j = 0; j < DM; j++) a += x[j] * w1[j * DI + t];
        sa[t] = fmaxf(a, 0.0f);
    }
    __syncthreads();
    if (t < DM) {
        float h = b2[t] + x[t];
        #pragma unroll 16
        for (int j = 0; j < DI; j++) h += sa[j] * w2[j * DM + t];
        sh[t] = h;
    }
    __syncthreads();
    if (t < 64) sr[t] = sh[t] + sh[t + 64];
    __syncthreads();
    if (t < 32) {
        float v = sr[t] + sr[t + 32];
        for (int o = 16; o; o >>= 1) v += __shfl_down_sync(0xffffffff, v, o);
        if (t == 0) sc[0] = v / (float)DM;
    }
    __syncthreads();
    float mu = sc[0];
    if (t < 64) {
        float d0 = sh[t] - mu, d1 = sh[t + 64] - mu;
        sr[t] = d0 * d0 + d1 * d1;
    }
    __syncthreads();
    if (t < 32) {
        float v = sr[t] + sr[t + 32];
        for (int o = 16; o; o >>= 1) v += __shfl_down_sync(0xffffffff, v, o);
        if (t == 0) sc[1] = sqrtf(v / (float)(DM - 1));
    }
    __syncthreads();
    if (t < DM) y[t] = (sh[t] - mu) / (sc[1] + LN_EPS) * lg[t] + lb[t];
    __syncthreads();
}

// ---------------- 32x32 tile GEMM with K-split across thread halves, N=1024 ----------------
// XPROJ=true: C = A@B + bih + bhh;  XPROJ=false (gates): C = A@B + xproj + attn@SW
template<int K, bool XPROJ>
__device__ __forceinline__ void gemm32x32(const float* __restrict__ A, const float* __restrict__ Bm,
        const float* __restrict__ bih, const float* __restrict__ bhh,
        float* __restrict__ C, float* sm, int t, int bid) {
    int rb = bid >> 5, cb = bid & 31;
    int kh = t >> 8, u = t & 255;
    int rl = u >> 3, c4 = (u & 7) * 4;
    int row = rb * 32 + rl, col = cb * 32 + c4;
    const int Kh = K / 2;
    const float* Ap = A + (size_t)row * K + kh * Kh;
    const float* Bp = Bm + (size_t)(kh * Kh) * 1024 + col;
    unsigned long long acc0 = 0ULL, acc1 = 0ULL;
    #pragma unroll 4
    for (int k4 = 0; k4 < Kh; k4 += 4) {
        float4 a4 = *(const float4*)(Ap + k4);
        {
            ulonglong2 bv = *(const ulonglong2*)(Bp + (size_t)(k4 + 0) * 1024);
            unsigned long long a2; FPACK2(a2, a4.x);
            FMA2(acc0, bv.x, a2); FMA2(acc1, bv.y, a2);
        }
        {
            ulonglong2 bv = *(const ulonglong2*)(Bp + (size_t)(k4 + 1) * 1024);
            unsigned long long a2; FPACK2(a2, a4.y);
            FMA2(acc0, bv.x, a2); FMA2(acc1, bv.y, a2);
        }
        {
            ulonglong2 bv = *(const ulonglong2*)(Bp + (size_t)(k4 + 2) * 1024);
            unsigned long long a2; FPACK2(a2, a4.z);
            FMA2(acc0, bv.x, a2); FMA2(acc1, bv.y, a2);
        }
        {
            ulonglong2 bv = *(const ulonglong2*)(Bp + (size_t)(k4 + 3) * 1024);
            unsigned long long a2; FPACK2(a2, a4.w);
            FMA2(acc0, bv.x, a2); FMA2(acc1, bv.y, a2);
        }
    }
    float o0, o1, o2, o3;
    UNPACK2(o0, o1, acc0); UNPACK2(o2, o3, acc1);
    float4* sp4 = (float4*)sm;
    if (kh == 1) sp4[u] = make_float4(o0, o1, o2, o3);
    __syncthreads();
    if (kh == 0) {
        float4 pv = sp4[u];
        o0 += pv.x; o1 += pv.y; o2 += pv.z; o3 += pv.w;
        if (XPROJ) {
            o0 += bih[col]   + bhh[col];
            o1 += bih[col+1] + bhh[col+1];
            o2 += bih[col+2] + bhh[col+2];
            o3 += bih[col+3] + bhh[col+3];
        } else {
            float4 xv = *(const float4*)&g_xproj[(size_t)row * 1024 + col];
            o0 += xv.x; o1 += xv.y; o2 += xv.z; o3 += xv.w;
            #pragma unroll
            for (int j = 0; j < FEW; j++) {
                float aj = g_attn[row * 8 + j];
                float4 sw = *(const float4*)&g_SW[j * 1024 + col];
                o0 += aj * sw.x; o1 += aj * sw.y; o2 += aj * sw.z; o3 += aj * sw.w;
            }
        }
        *(float4*)&C[(size_t)row * 1024 + col] = make_float4(o0, o1, o2, o3);
    }
    __syncthreads();
}

// ---------------- LSTM elementwise + attention (block = batch row, 512 threads) ----------------
__device__ __forceinline__ void lstm_elt(const float* __restrict__ gates, float* __restrict__ out,
                                         int first, int last, int b, int t, float* sm) {
    float* sh = sm;           // 128
    float* slog = sm + 128;   // 8
    float* sattn = sm + 136;  // 8
    if (t < 256) {
        const float* gr = gates + (size_t)b * 1024;
        float gi = gr[t], gf = gr[256 + t], gg = gr[512 + t], go = gr[768 + t];
        float cp = first ? 0.0f : g_c[b * HID + t];
        float cn = sigmoidf_(gf) * cp + sigmoidf_(gi) * tanhf(gg);
        g_c[b * HID + t] = cn;
        if (t < DM) sh[t] = g_query_g[b * DM + t] + sigmoidf_(go) * tanhf(cn);
    }
    __syncthreads();
    int w = t >> 5, lane = t & 31;
    if (w < FEW) {
        const float* sup = g_support_g + w * DM;
        float v = sh[lane] * sup[lane] + sh[lane+32] * sup[lane+32]
                + sh[lane+64] * sup[lane+64] + sh[lane+96] * sup[lane+96];
        for (int o = 16; o; o >>= 1) v += __shfl_down_sync(0xffffffff, v, o);
        if (lane == 0) slog[w] = v;
    }
    __syncthreads();
    if (last) {
        if (t < FEW) out[b * FEW + t] = slog[t];
        return;
    }
    if (t == 0) {
        float mx = slog[0];
        #pragma unroll
        for (int j = 1; j < FEW; j++) mx = fmaxf(mx, slog[j]);
        float s = 0.0f, e[FEW];
        #pragma unroll
        for (int j = 0; j < FEW; j++) { e[j] = expf(slog[j] - mx); s += e[j]; }
        #pragma unroll
        for (int j = 0; j < FEW; j++) sattn[j] = e[j] / s;
    }
    __syncthreads();
    if (t < DM) g_h[b * DM + t] = sh[t];
    if (t < 8)  g_attn[b * 8 + t] = (t < FEW) ? sattn[t] : 0.0f;
}

// ---------------- THE kernel ----------------
__global__ __launch_bounds__(NT, 1) void mega_kernel(
        const int2* __restrict__ ql, const int2* __restrict__ qr,
        const int2* __restrict__ sl, const int2* __restrict__ sr,
        const float* __restrict__ qld, const float* __restrict__ qrd,
        const float* __restrict__ sld, const float* __restrict__ srd,
        const float* __restrict__ ent_emb, const float* __restrict__ rel_mat,
        const float* __restrict__ gcn_w, const float* __restrict__ gcn_wb, const float* __restrict__ gcn_b,
        const float* __restrict__ w1, const float* __restrict__ b1,
        const float* __restrict__ w2, const float* __restrict__ b2,
        const float* __restrict__ lg, const float* __restrict__ lb,
        const float* __restrict__ wih, const float* __restrict__ whh,
        const float* __restrict__ bih, const float* __restrict__ bhh,
        float* __restrict__ out) {
    __shared__ __align__(16) float smem[8448];   // 33.8KB union
    __shared__ unsigned long long s_base;
    int t = threadIdx.x, bid = blockIdx.x;
    if (t == 0) {
        unsigned long long c;
        asm volatile("ld.global.acquire.gpu.u64 %0, [%1];" : "=l"(c) : "l"(&g_barcnt) : "memory");
        s_base = (c / (unsigned long long)(GRID * NBAR)) * (unsigned long long)(GRID * NBAR);
    }
    __syncthreads();
    unsigned long long bbase = s_base;

    // ===== Stage 0: scatter into padded per-rel bins =====
    {
        int lo = bid * 370, hi = min(lo + 370, NPTOT);
        for (int idx = lo + t; idx < hi; idx += NT) {
            int2 c;
            if (idx < NPQ)                 c = ql[idx];
            else if (idx < 2*NPQ)          c = qr[idx - NPQ];
            else if (idx < 2*NPQ + NPS)    c = sl[idx - 2*NPQ];
            else                           c = sr[idx - 2*NPQ - NPS];
            int pos = atomicAdd(&g_cnt[c.x], 1);
            if (pos < CAP) g_pairs[c.x * CAP + pos] = make_int2(idx, c.y);
        }
    }
    grid_bar(bbase, 0);

    // ===== Stage 1: binned RESCAL matvecs (16 warps, FFMA2, no atomics) =====
    {
        float* sR   = smem;                  // 64*68 = 4352
        float* sE01 = smem + 4352;           // 16*128
        float* sE23 = smem + 6400;           // 16*128
        int w = t >> 5, lane = t & 31;
        for (int r = bid; r < NRELS; r += GRID) {
            int cnt = g_cnt[r];
            __syncthreads();
            if (t == 0) g_cnt[r] = 0;
            if (cnt == 0) continue;
            if (cnt > CAP) cnt = CAP;
            const float* R = rel_mat + (size_t)r * 4096;
            for (int i = t; i < 4096; i += NT) sR[(i >> 6) * 68 + (i & 63)] = R[i];
            __syncthreads();
            float* e01 = sE01 + w * 128;
            float* e23 = sE23 + w * 128;
            for (int base = w * 4; base < cnt; base += 64) {
                int np = min(4, cnt - base);
                int origs[4];
                #pragma unroll
                for (int p = 0; p < 4; p++) {
                    if (p < np) {
                        int2 pr = g_pairs[r * CAP + base + p];
                        origs[p] = pr.x;
                        float2 v = ((const float2*)(ent_emb + (size_t)pr.y * 64))[lane];
                        float* dstE = (p < 2) ? e01 : e23;
                        int pp = p & 1;
                        dstE[4*lane + pp]     = v.x;
                        dstE[4*lane + 2 + pp] = v.y;
                    }
                }
                __syncwarp();
                unsigned long long aA01=0, aA23=0, aB01=0, aB23=0;
                #pragma unroll
                for (int j4 = 0; j4 < 64; j4 += 4) {
                    float4 rA = *(const float4*)&sR[lane * 68 + j4];
                    float4 rB = *(const float4*)&sR[(lane + 32) * 68 + j4];
                    ulonglong2 E01a = *(const ulonglong2*)(e01 + j4*2);
                    ulonglong2 E01b = *(const ulonglong2*)(e01 + j4*2 + 4);
                    ulonglong2 E23a = *(const ulonglong2*)(e23 + j4*2);
                    ulonglong2 E23b = *(const ulonglong2*)(e23 + j4*2 + 4);
                    unsigned long long dA, dB;
                    FPACK2(dA, rA.x); FPACK2(dB, rB.x);
                    FMA2(aA01, E01a.x, dA); FMA2(aA23, E23a.x, dA);
                    FMA2(aB01, E01a.x, dB); FMA2(aB23, E23a.x, dB);
                    FPACK2(dA, rA.y); FPACK2(dB, rB.y);
                    FMA2(aA01, E01a.y, dA); FMA2(aA23, E23a.y, dA);
                    FMA2(aB01, E01a.y, dB); FMA2(aB23, E23a.y, dB);
                    FPACK2(dA, rA.z); FPACK2(dB, rB.z);
                    FMA2(aA01, E01b.x, dA); FMA2(aA23, E23b.x, dA);
                    FMA2(aB01, E01b.x, dB); FMA2(aB23, E23b.x, dB);
                    FPACK2(dA, rA.w); FPACK2(dB, rB.w);
                    FMA2(aA01, E01b.y, dA); FMA2(aA23, E23b.y, dA);
                    FMA2(aB01, E01b.y, dB); FMA2(aB23, E23b.y, dB);
                }
                float accA[4], accB[4];
                UNPACK2(accA[0], accA[1], aA01); UNPACK2(accA[2], accA[3], aA23);
                UNPACK2(accB[0], accB[1], aB01); UNPACK2(accB[2], accB[3], aB23);
                #pragma unroll
                for (int p = 0; p < 4; p++) {
                    if (p < np) {
                        float* dst = g_msg + (size_t)origs[p] * 64;
                        dst[lane]      = accA[p];
                        dst[lane + 32] = accB[p];
                    }
                }
                __syncwarp();
            }
        }
    }
    grid_bar(bbase, 1);

    // ===== Stage 2: gcn finalize + support encoder, fused per row =====
    if (bid < Bq) {
        gcn_row(bid * NN, NPQ + bid * NN, qld[bid], qrd[bid], gcn_w, gcn_wb, gcn_b, smem, t);
        supp_row(g_query_g + bid * DM, w1, b1, w2, b2, lg, lb, smem, t);
    } else if (bid < Bq + FEW) {
        int s = bid - Bq;
        gcn_row(2*NPQ + s * NN, 2*NPQ + NPS + s * NN, sld[s], srd[s], gcn_w, gcn_wb, gcn_b, smem, t);
        supp_row(g_support_g + s * DM, w1, b1, w2, b2, lg, lb, smem, t);
    }
    grid_bar(bbase, 2);

    // ===== Stage 3: x_proj = query_g @ wih + bih + bhh ; SW = support_g @ whh[128:] =====
    if (bid < 128) {
        gemm32x32<128, true>(g_query_g, wih, bih, bhh, g_xproj, smem, t, bid);
    } else {
        int cb = bid - 128;   // 0..15
        if (t < 320) {
            int j = t >> 6, col = cb * 64 + (t & 63);
            float acc = 0.0f;
            #pragma unroll 8
            for (int k = 0; k < 128; k++)
                acc += g_support_g[j * 128 + k] * whh[(size_t)(128 + k) * 1024 + col];
            g_SW[j * 1024 + col] = acc;
        }
    }
    grid_bar(bbase, 3);

    // ===== Stage 4: LSTM step 0 (h_r = 0 -> gates = x_proj) =====
    if (bid < Bq) lstm_elt(g_xproj, out, 1, 0, bid, t, smem);
    grid_bar(bbase, 4);

    // ===== Stages 5..9: LSTM steps 1..3 (K=128 GEMM + rank-5 correction) =====
    #pragma unroll
    for (int s = 1; s < 4; s++) {
        if (bid < 128)
            gemm32x32<128, false>(g_h, whh, nullptr, nullptr, g_gates, smem, t, bid);
        grid_bar(bbase, 2 * s + 3);
        if (bid < Bq) lstm_elt(g_gates, out, 0, (s == 3) ? 1 : 0, bid, t, smem);
        if (s < 3) grid_bar(bbase, 2 * s + 4);
    }
}

// ---------------- host ----------------
extern "C" void kernel_launch(void* const* d_in, const int* in_sizes, int n_in,
                              void* d_out, int out_size) {
    const int2*  ql     = (const int2*)d_in[0];
    const int2*  qr     = (const int2*)d_in[1];
    const int2*  sl     = (const int2*)d_in[2];
    const int2*  sr     = (const int2*)d_in[3];
    const float* qld    = (const float*)d_in[4];
    const float* qrd    = (const float*)d_in[5];
    const float* sld    = (const float*)d_in[6];
    const float* srd    = (const float*)d_in[7];
    const float* ent    = (const float*)d_in[8];
    const float* relm   = (const float*)d_in[9];
    const float* gcn_w  = (const float*)d_in[10];
    const float* gcn_wb = (const float*)d_in[11];
    const float* gcn_b  = (const float*)d_in[12];
    const float* se_w1  = (const float*)d_in[13];
    const float* se_b1  = (const float*)d_in[14];
    const float* se_w2  = (const float*)d_in[15];
    const float* se_b2  = (const float*)d_in[16];
    const float* ln_g   = (const float*)d_in[17];
    const float* ln_b   = (const float*)d_in[18];
    const float* wih    = (const float*)d_in[19];
    const float* whh    = (const float*)d_in[20];
    const float* bih    = (const float*)d_in[21];
    const float* bhh    = (const float*)d_in[22];
    float* out = (float*)d_out;

    mega_kernel<<<GRID, NT>>>(ql, qr, sl, sr, qld, qrd, sld, srd, ent, relm,
                              gcn_w, gcn_wb, gcn_b, se_w1, se_b1, se_w2, se_b2,
                              ln_g, ln_b, wih, whh, bih, bhh, out);
}

// round 6
// speedup vs baseline: 1.8808x; 1.0198x over previous
#include <cuda_runtime.h>
#include <math.h>
#include <stdint.h>

#define Dd 64
#define DM 128
#define DI 256
#define HID 256
#define Bq 128
#define NN 200
#define FEW 5
#define NRELS 500
#define NPQ (Bq*NN)
#define NPS (FEW*NN)
#define NPTOT (2*NPQ + 2*NPS)   // 53200
#define CAP 512
#define LN_EPS 0.001f
#define NBAR 4
#define GRID 148
#define NT 512
#define SCHUNK 360              // 148*360 >= 53200

// lstm smem layout (float offsets)
#define SXP   0       // 4096  xproj 4x1024
#define SPART 4096    // 4096  gemm partial / gates 4x1024
#define SHT   8192    // 512   h transposed [128][4] (also query_g^T for xproj)
#define SQ    8704    // 512   query_g rows [4][128]
#define SSUP  9216    // 640   support_g [5][128]
#define SLOG  9856    // 32    [4][8]
#define SATT  9888    // 32
#define SRED  9920    // 16

// ---------------- device scratch ----------------
__device__ int   g_cnt[512];                 // zero-init; self-zeroed each pass
__device__ int2  g_pairs[NRELS*CAP];
__device__ float g_msg[(size_t)NPTOT*64];
__device__ float g_query_g[Bq*DM];
__device__ float g_support_g[FEW*DM];
__device__ float g_SW[FEW*1024];             // support_g @ whh[128:256,:]
__device__ int   g_relctr;                   // work queue; reset each launch in stage 0
__device__ unsigned long long g_barcnt;      // monotonic, never reset

__device__ __forceinline__ float sigmoidf_(float x) { return 1.0f / (1.0f + expf(-x)); }

// packed fp32x2 helpers (Blackwell FFMA2)
#define FPACK2(d, f)      asm("mov.b64 %0, {%1, %1};" : "=l"(d) : "f"(f))
#define FMA2(acc, e, r)   asm("fma.rn.f32x2 %0, %1, %2, %3;" : "=l"(acc) : "l"(e), "l"(r), "l"(acc))
#define UNPACK2(lo, hi, v) asm("mov.b64 {%0, %1}, %2;" : "=f"(lo), "=f"(hi) : "l"(v))

// ---------------- grid barrier: monotonic epoch counter ----------------
__device__ __forceinline__ void grid_bar(unsigned long long base, int k) {
    __syncthreads();
    if (threadIdx.x == 0) {
        __threadfence();
        atomicAdd(&g_barcnt, 1ULL);
        unsigned long long target = base + (unsigned long long)GRID * (unsigned long long)(k + 1);
        unsigned long long v;
        do {
            asm volatile("ld.global.acquire.gpu.u64 %0, [%1];" : "=l"(v) : "l"(&g_barcnt) : "memory");
        } while (v < target);
        __threadfence();
    }
    __syncthreads();
}

// ---------------- gcn row (512 threads): reduce 200 msgs per half, matvec, tanh -> sm x[128]
__device__ __forceinline__ void gcn_row(int baseL, int baseR, float degL, float degR,
        const float* __restrict__ gcn_w, const float* __restrict__ gcn_wb, const float* __restrict__ gcn_b,
        float* sm, int t) {
    float* sp   = sm;          // 512
    float* msum = sm + 512;    // 128
    float* x    = sm + 640;    // 128
    {
        int h = t >> 8, rem = t & 255, rg = rem >> 6, c = rem & 63;
        int base = h ? baseR : baseL;
        float part = 0.0f;
        #pragma unroll 10
        for (int j = rg; j < NN; j += 4) part += g_msg[(size_t)(base + j) * 64 + c];
        sp[t] = part;
    }
    __syncthreads();
    if (t < 128) {
        int b0 = (t >> 6) * 256, o = t & 63;
        msum[t] = sp[b0 + o] + sp[b0 + 64 + o] + sp[b0 + 128 + o] + sp[b0 + 192 + o];
    }
    __syncthreads();
    if (t < 128) {
        int hh = t >> 6, o = t & 63;
        float acc = 0.0f;
        #pragma unroll 16
        for (int i = 0; i < 64; i++) acc += msum[hh * 64 + i] * gcn_w[i * 64 + o];
        acc += (float)NN * (gcn_wb[o] + gcn_b[o]);
        x[t] = tanhf(acc / (hh ? degR : degL));
    }
    __syncthreads();
}

// ---------------- support encoder row: x(sm+640) -> y(global)
__device__ __forceinline__ void supp_row(float* __restrict__ y,
        const float* __restrict__ w1, const float* __restrict__ b1,
        const float* __restrict__ w2, const float* __restrict__ b2,
        const float* __restrict__ lg, const float* __restrict__ lb,
        float* sm, int t) {
    float* x  = sm + 640;    // 128
    float* sa = sm + 768;    // 256
    float* sh = sm + 1024;   // 128
    float* sr = sm + 1152;   // 64
    float* sc = sm + 1216;   // 2
    if (t < DI) {
        float a = b1[t];
        #pragma unroll 16
        for (int j = 0; j < DM; j++) a += x[j] * w1[j * DI + t];
        sa[t] = fmaxf(a, 0.0f);
    }
    __syncthreads();
    if (t < DM) {
        float h = b2[t] + x[t];
        #pragma unroll 16
        for (int j = 0; j < DI; j++) h += sa[j] * w2[j * DM + t];
        sh[t] = h;
    }
    __syncthreads();
    if (t < 64) sr[t] = sh[t] + sh[t + 64];
    __syncthreads();
    if (t < 32) {
        float v = sr[t] + sr[t + 32];
        for (int o = 16; o; o >>= 1) v += __shfl_down_sync(0xffffffff, v, o);
        if (t == 0) sc[0] = v / (float)DM;
    }
    __syncthreads();
    float mu = sc[0];
    if (t < 64) {
        float d0 = sh[t] - mu, d1 = sh[t + 64] - mu;
        sr[t] = d0 * d0 + d1 * d1;
    }
    __syncthreads();
    if (t < 32) {
        float v = sr[t] + sr[t + 32];
        for (int o = 16; o; o >>= 1) v += __shfl_down_sync(0xffffffff, v, o);
        if (t == 0) sc[1] = sqrtf(v / (float)(DM - 1));
    }
    __syncthreads();
    if (t < DM) y[t] = (sh[t] - mu) / (sc[1] + LN_EPS) * lg[t] + lb[t];
    __syncthreads();
}

// ---------------- in-block 4-row GEMM vs 1024-col weight (K=128, k-split halves) ----------------
// XPROJ: out -> SXP, += bih+bhh.  else: out -> SPART, += SXP + attn@SW (rank-5 correction)
template<bool XPROJ>
__device__ __forceinline__ void gemm4(float* sm, const float* __restrict__ Bmat,
        const float* __restrict__ bih, const float* __restrict__ bhh, int t) {
    int kh = t >> 8, u = t & 255, c4 = u * 4;
    const float* Bp = Bmat + (size_t)(kh * 64) * 1024 + c4;
    const float* Ap = sm + SHT + kh * 64 * 4;
    unsigned long long acc[8];
    #pragma unroll
    for (int i = 0; i < 8; i++) acc[i] = 0ULL;
    #pragma unroll 8
    for (int k = 0; k < 64; k++) {
        float4 a4 = *(const float4*)(Ap + k * 4);
        ulonglong2 bv = *(const ulonglong2*)(Bp + (size_t)k * 1024);
        unsigned long long ar;
        FPACK2(ar, a4.x); FMA2(acc[0], bv.x, ar); FMA2(acc[1], bv.y, ar);
        FPACK2(ar, a4.y); FMA2(acc[2], bv.x, ar); FMA2(acc[3], bv.y, ar);
        FPACK2(ar, a4.z); FMA2(acc[4], bv.x, ar); FMA2(acc[5], bv.y, ar);
        FPACK2(ar, a4.w); FMA2(acc[6], bv.x, ar); FMA2(acc[7], bv.y, ar);
    }
    if (kh == 1) {
        #pragma unroll
        for (int r = 0; r < 4; r++) {
            float o0, o1, o2, o3;
            UNPACK2(o0, o1, acc[r*2]); UNPACK2(o2, o3, acc[r*2+1]);
            *(float4*)&sm[SPART + r * 1024 + c4] = make_float4(o0, o1, o2, o3);
        }
    }
    __syncthreads();
    if (kh == 0) {
        float4 sw[FEW];
        float4 bb;
        if (XPROJ) {
            bb = make_float4(bih[c4]+bhh[c4], bih[c4+1]+bhh[c4+1],
                             bih[c4+2]+bhh[c4+2], bih[c4+3]+bhh[c4+3]);
        } else {
            #pragma unroll
            for (int j = 0; j < FEW; j++) sw[j] = *(const float4*)&g_SW[j * 1024 + c4];
        }
        #pragma unroll
        for (int r = 0; r < 4; r++) {
            float o0, o1, o2, o3;
            UNPACK2(o0, o1, acc[r*2]); UNPACK2(o2, o3, acc[r*2+1]);
            float4 pv = *(const float4*)&sm[SPART + r * 1024 + c4];
            o0 += pv.x; o1 += pv.y; o2 += pv.z; o3 += pv.w;
            if (XPROJ) {
                o0 += bb.x; o1 += bb.y; o2 += bb.z; o3 += bb.w;
                *(float4*)&sm[SXP + r * 1024 + c4] = make_float4(o0, o1, o2, o3);
            } else {
                float4 xv = *(const float4*)&sm[SXP + r * 1024 + c4];
                o0 += xv.x; o1 += xv.y; o2 += xv.z; o3 += xv.w;
                #pragma unroll
                for (int j = 0; j < FEW; j++) {
                    float aj = sm[SATT + r * 8 + j];
                    o0 += aj * sw[j].x; o1 += aj * sw[j].y;
                    o2 += aj * sw[j].z; o3 += aj * sw[j].w;
                }
                *(float4*)&sm[SPART + r * 1024 + c4] = make_float4(o0, o1, o2, o3);
            }
        }
    }
    __syncthreads();
}

// ---------------- LSTM elementwise + attention for 4 rows, fully in-block ----------------
__device__ __forceinline__ void elt4(float* sm, const float* gbase, float& c0, float& c1,
                                     int t, int row0, int last, float* __restrict__ out) {
    int r = t >> 7, u = t & 127, u2 = u * 2;
    const float* gp = gbase + r * 1024;
    float gi0 = gp[u2],       gi1 = gp[u2 + 1];
    float gf0 = gp[256 + u2], gf1 = gp[257 + u2];
    float gg0 = gp[512 + u2], gg1 = gp[513 + u2];
    float go0 = gp[768 + u2], go1 = gp[769 + u2];
    c0 = sigmoidf_(gf0) * c0 + sigmoidf_(gi0) * tanhf(gg0);
    c1 = sigmoidf_(gf1) * c1 + sigmoidf_(gi1) * tanhf(gg1);
    if (u2 < 128) {
        float h0 = sm[SQ + r * 128 + u2]     + sigmoidf_(go0) * tanhf(c0);
        float h1 = sm[SQ + r * 128 + u2 + 1] + sigmoidf_(go1) * tanhf(c1);
        sm[SHT + u2 * 4 + r]       = h0;
        sm[SHT + (u2 + 1) * 4 + r] = h1;
    }
    __syncthreads();
    float hv = sm[SHT + u * 4 + r];
    int lane = t & 31, wid = t >> 5;
    #pragma unroll
    for (int j = 0; j < FEW; j++) {
        float p = hv * sm[SSUP + j * 128 + u];
        for (int o = 16; o; o >>= 1) p += __shfl_down_sync(0xffffffff, p, o);
        if (lane == 0) sm[SRED + wid] = p;
        __syncthreads();
        if (t < 4) sm[SLOG + t * 8 + j] = sm[SRED + 4*t] + sm[SRED + 4*t + 1]
                                        + sm[SRED + 4*t + 2] + sm[SRED + 4*t + 3];
        __syncthreads();
    }
    if (last) {
        if (t < 4) {
            #pragma unroll
            for (int j = 0; j < FEW; j++) out[(row0 + t) * FEW + j] = sm[SLOG + t * 8 + j];
        }
        return;
    }
    if (t < 4) {
        float mx = sm[SLOG + t * 8];
        #pragma unroll
        for (int j = 1; j < FEW; j++) mx = fmaxf(mx, sm[SLOG + t * 8 + j]);
        float s = 0.0f, e[FEW];
        #pragma unroll
        for (int j = 0; j < FEW; j++) { e[j] = expf(sm[SLOG + t * 8 + j] - mx); s += e[j]; }
        #pragma unroll
        for (int j = 0; j < FEW; j++) sm[SATT + t * 8 + j] = e[j] / s;
    }
    __syncthreads();
}

// ---------------- THE kernel ----------------
__global__ __launch_bounds__(NT, 1) void mega_kernel(
        const int2* __restrict__ ql, const int2* __restrict__ qr,
        const int2* __restrict__ sl, const int2* __restrict__ sr,
        const float* __restrict__ qld, const float* __restrict__ qrd,
        const float* __restrict__ sld, const float* __restrict__ srd,
        const float* __restrict__ ent_emb, const float* __restrict__ rel_mat,
        const float* __restrict__ gcn_w, const float* __restrict__ gcn_wb, const float* __restrict__ gcn_b,
        const float* __restrict__ w1, const float* __restrict__ b1,
        const float* __restrict__ w2, const float* __restrict__ b2,
        const float* __restrict__ lg, const float* __restrict__ lb,
        const float* __restrict__ wih, const float* __restrict__ whh,
        const float* __restrict__ bih, const float* __restrict__ bhh,
        float* __restrict__ out) {
    __shared__ __align__(16) float smem[10240];   // 40KB union
    __shared__ unsigned long long s_base;
    __shared__ int s_r;
    int t = threadIdx.x, bid = blockIdx.x;
    if (t == 0) {
        unsigned long long c;
        asm volatile("ld.global.acquire.gpu.u64 %0, [%1];" : "=l"(c) : "l"(&g_barcnt) : "memory");
        s_base = (c / (unsigned long long)(GRID * NBAR)) * (unsigned long long)(GRID * NBAR);
    }
    __syncthreads();
    unsigned long long bbase = s_base;

    // ===== Stage 0: scatter into padded per-rel bins; reset work queue =====
    if (bid == 0 && t == 0) g_relctr = 0;
    {
        int lo = bid * SCHUNK, hi = min(lo + SCHUNK, NPTOT);
        for (int idx = lo + t; idx < hi; idx += NT) {
            int2 c;
            if (idx < NPQ)                 c = ql[idx];
            else if (idx < 2*NPQ)          c = qr[idx - NPQ];
            else if (idx < 2*NPQ + NPS)    c = sl[idx - 2*NPQ];
            else                           c = sr[idx - 2*NPQ - NPS];
            int pos = atomicAdd(&g_cnt[c.x], 1);
            if (pos < CAP) g_pairs[c.x * CAP + pos] = make_int2(idx, c.y);
        }
    }
    grid_bar(bbase, 0);

    // ===== Stage 1: binned RESCAL matvecs, dynamic rel scheduling =====
    {
        float* sR   = smem;                  // 64*68 = 4352
        float* sE01 = smem + 4352;           // 16*128
        float* sE23 = smem + 6400;           // 16*128
        int w = t >> 5, lane = t & 31;
        for (;;) {
            if (t == 0) s_r = atomicAdd(&g_relctr, 1);
            __syncthreads();
            int r = s_r;
            if (r >= NRELS) break;
            int cnt = g_cnt[r];
            __syncthreads();
            if (t == 0) g_cnt[r] = 0;
            if (cnt > 0) {
                if (cnt > CAP) cnt = CAP;
                const float* R = rel_mat + (size_t)r * 4096;
                for (int i = t; i < 4096; i += NT) sR[(i >> 6) * 68 + (i & 63)] = R[i];
                __syncthreads();
                float* e01 = sE01 + w * 128;
                float* e23 = sE23 + w * 128;
                for (int base = w * 4; base < cnt; base += 64) {
                    int np = min(4, cnt - base);
                    int origs[4];
                    #pragma unroll
                    for (int p = 0; p < 4; p++) {
                        if (p < np) {
                            int2 pr = g_pairs[r * CAP + base + p];
                            origs[p] = pr.x;
                            float2 v = ((const float2*)(ent_emb + (size_t)pr.y * 64))[lane];
                            float* dstE = (p < 2) ? e01 : e23;
                            int pp = p & 1;
                            dstE[4*lane + pp]     = v.x;
                            dstE[4*lane + 2 + pp] = v.y;
                        }
                    }
                    __syncwarp();
                    unsigned long long aA01=0, aA23=0, aB01=0, aB23=0;
                    #pragma unroll
                    for (int j4 = 0; j4 < 64; j4 += 4) {
                        float4 rA = *(const float4*)&sR[lane * 68 + j4];
                        float4 rB = *(const float4*)&sR[(lane + 32) * 68 + j4];
                        ulonglong2 E01a = *(const ulonglong2*)(e01 + j4*2);
                        ulonglong2 E01b = *(const ulonglong2*)(e01 + j4*2 + 4);
                        ulonglong2 E23a = *(const ulonglong2*)(e23 + j4*2);
                        ulonglong2 E23b = *(const ulonglong2*)(e23 + j4*2 + 4);
                        unsigned long long dA, dB;
                        FPACK2(dA, rA.x); FPACK2(dB, rB.x);
                        FMA2(aA01, E01a.x, dA); FMA2(aA23, E23a.x, dA);
                        FMA2(aB01, E01a.x, dB); FMA2(aB23, E23a.x, dB);
                        FPACK2(dA, rA.y); FPACK2(dB, rB.y);
                        FMA2(aA01, E01a.y, dA); FMA2(aA23, E23a.y, dA);
                        FMA2(aB01, E01a.y, dB); FMA2(aB23, E23a.y, dB);
                        FPACK2(dA, rA.z); FPACK2(dB, rB.z);
                        FMA2(aA01, E01b.x, dA); FMA2(aA23, E23b.x, dA);
                        FMA2(aB01, E01b.x, dB); FMA2(aB23, E23b.x, dB);
                        FPACK2(dA, rA.w); FPACK2(dB, rB.w);
                        FMA2(aA01, E01b.y, dA); FMA2(aA23, E23b.y, dA);
                        FMA2(aB01, E01b.y, dB); FMA2(aB23, E23b.y, dB);
                    }
                    float accA[4], accB[4];
                    UNPACK2(accA[0], accA[1], aA01); UNPACK2(accA[2], accA[3], aA23);
                    UNPACK2(accB[0], accB[1], aB01); UNPACK2(accB[2], accB[3], aB23);
                    #pragma unroll
                    for (int p = 0; p < 4; p++) {
                        if (p < np) {
                            float* dst = g_msg + (size_t)origs[p] * 64;
                            dst[lane]      = accA[p];
                            dst[lane + 32] = accB[p];
                        }
                    }
                    __syncwarp();
                }
            }
            __syncthreads();   // sR/sE reuse + s_r rewrite safety
        }
    }
    grid_bar(bbase, 1);

    // ===== Stage 2: gcn finalize + support encoder, fused per row =====
    if (bid < Bq) {
        gcn_row(bid * NN, NPQ + bid * NN, qld[bid], qrd[bid], gcn_w, gcn_wb, gcn_b, smem, t);
        supp_row(g_query_g + bid * DM, w1, b1, w2, b2, lg, lb, smem, t);
    } else if (bid < Bq + FEW) {
        int s = bid - Bq;
        gcn_row(2*NPQ + s * NN, 2*NPQ + NPS + s * NN, sld[s], srd[s], gcn_w, gcn_wb, gcn_b, smem, t);
        supp_row(g_support_g + s * DM, w1, b1, w2, b2, lg, lb, smem, t);
    }
    grid_bar(bbase, 2);

    // ===== Stage 3: blocks 0-31: xproj + LSTM step 0; blocks 32-47: SW =====
    int row0 = bid * 4;
    float c0 = 0.0f, c1 = 0.0f;
    if (bid < 32) {
        {   // load query_g rows (transposed + plain) and support_g into smem
            int r = t >> 7, k = t & 127;
            float v = g_query_g[(size_t)(row0 + r) * 128 + k];
            smem[SHT + k * 4 + r] = v;
            smem[SQ + r * 128 + k] = v;
            for (int i = t; i < FEW * 128; i += NT) smem[SSUP + i] = g_support_g[i];
        }
        __syncthreads();
        gemm4<true>(smem, wih, bih, bhh, t);
        elt4(smem, smem + SXP, c0, c1, t, row0, 0, out);
    } else if (bid < 48) {
        int cb = bid - 32;   // 0..15
        if (t < 320) {
            int j = t >> 6, col = cb * 64 + (t & 63);
            float acc = 0.0f;
            #pragma unroll 8
            for (int k = 0; k < 128; k++)
                acc += g_support_g[j * 128 + k] * whh[(size_t)(128 + k) * 1024 + col];
            g_SW[j * 1024 + col] = acc;
        }
    }
    grid_bar(bbase, 3);

    // ===== LSTM steps 1..3: fully intra-block, no grid barriers =====
    if (bid < 32) {
        #pragma unroll
        for (int s = 1; s < 4; s++) {
            gemm4<false>(smem, whh, nullptr, nullptr, t);
            elt4(smem, smem + SPART, c0, c1, t, row0, (s == 3) ? 1 : 0, out);
        }
    }
}

// ---------------- host ----------------
extern "C" void kernel_launch(void* const* d_in, const int* in_sizes, int n_in,
                              void* d_out, int out_size) {
    const int2*  ql     = (const int2*)d_in[0];
    const int2*  qr     = (const int2*)d_in[1];
    const int2*  sl     = (const int2*)d_in[2];
    const int2*  sr     = (const int2*)d_in[3];
    const float* qld    = (const float*)d_in[4];
    const float* qrd    = (const float*)d_in[5];
    const float* sld    = (const float*)d_in[6];
    const float* srd    = (const float*)d_in[7];
    const float* ent    = (const float*)d_in[8];
    const float* relm   = (const float*)d_in[9];
    const float* gcn_w  = (const float*)d_in[10];
    const float* gcn_wb = (const float*)d_in[11];
    const float* gcn_b  = (const float*)d_in[12];
    const float* se_w1  = (const float*)d_in[13];
    const float* se_b1  = (const float*)d_in[14];
    const float* se_w2  = (const float*)d_in[15];
    const float* se_b2  = (const float*)d_in[16];
    const float* ln_g   = (const float*)d_in[17];
    const float* ln_b   = (const float*)d_in[18];
    const float* wih    = (const float*)d_in[19];
    const float* whh    = (const float*)d_in[20];
    const float* bih    = (const float*)d_in[21];
    const float* bhh    = (const float*)d_in[22];
    float* out = (float*)d_out;

    mega_kernel<<<GRID, NT>>>(ql, qr, sl, sr, qld, qrd, sld, srd, ent, relm,
                              gcn_w, gcn_wb, gcn_b, se_w1, se_b1, se_w2, se_b2,
                              ln_g, ln_b, wih, whh, bih, bhh, out);
}

// round 7
// speedup vs baseline: 1.8823x; 1.0008x over previous
#include <cuda_runtime.h>
#include <math.h>
#include <stdint.h>

#define Dd 64
#define DM 128
#define DI 256
#define HID 256
#define Bq 128
#define NN 200
#define FEW 5
#define NRELS 500
#define NPQ (Bq*NN)
#define NPS (FEW*NN)
#define NPTOT (2*NPQ + 2*NPS)   // 53200
#define CAP 512
#define LN_EPS 0.001f
#define NBAR 4
#define GRID 148
#define NT 512
#define SCHUNK 360              // 148*360 >= 53200

// lstm smem layout (float offsets)
#define SXP   0       // 4096  xproj 4x1024
#define SPART 4096    // 4096  gemm partial / gates 4x1024
#define SHT   8192    // 512   h transposed [128][4] (also query_g^T for xproj)
#define SQ    8704    // 512   query_g rows [4][128]
#define SSUP  9216    // 640   support_g [5][128]
#define SLOG  9856    // 32    [4][8]
#define SATT  9888    // 32
#define SRED  9920    // 16

// ---------------- device scratch ----------------
__device__ int   g_cnt[512];                 // zero-init; self-zeroed each pass
__device__ int2  g_pairs[NRELS*CAP];
__device__ float g_msg[(size_t)NPTOT*64];
__device__ float g_query_g[Bq*DM];
__device__ float g_support_g[FEW*DM];
__device__ float g_SW[FEW*1024];             // support_g @ whh[128:256,:]
__device__ int   g_relctr;                   // work queue; reset each launch in stage 0
__device__ unsigned long long g_barcnt;      // monotonic, never reset

__device__ __forceinline__ float sigmoidf_(float x) { return 1.0f / (1.0f + expf(-x)); }

// packed fp32x2 helpers (Blackwell FFMA2)
#define FPACK2(d, f)      asm("mov.b64 %0, {%1, %1};" : "=l"(d) : "f"(f))
#define FMA2(acc, e, r)   asm("fma.rn.f32x2 %0, %1, %2, %3;" : "=l"(acc) : "l"(e), "l"(r), "l"(acc))
#define UNPACK2(lo, hi, v) asm("mov.b64 {%0, %1}, %2;" : "=f"(lo), "=f"(hi) : "l"(v))

// ---------------- grid barrier: monotonic epoch counter ----------------
__device__ __forceinline__ void grid_bar(unsigned long long base, int k) {
    __syncthreads();
    if (threadIdx.x == 0) {
        __threadfence();
        atomicAdd(&g_barcnt, 1ULL);
        unsigned long long target = base + (unsigned long long)GRID * (unsigned long long)(k + 1);
        unsigned long long v;
        do {
            asm volatile("ld.global.acquire.gpu.u64 %0, [%1];" : "=l"(v) : "l"(&g_barcnt) : "memory");
        } while (v < target);
        __threadfence();
    }
    __syncthreads();
}

// ---------------- gcn row (512 threads): reduce 200 msgs per half, matvec, tanh -> sm x[128]
__device__ __forceinline__ void gcn_row(int baseL, int baseR, float degL, float degR,
        const float* __restrict__ gcn_w, const float* __restrict__ gcn_wb, const float* __restrict__ gcn_b,
        float* sm, int t) {
    float* sp   = sm;          // 512
    float* msum = sm + 512;    // 128
    float* x    = sm + 640;    // 128
    {
        int h = t >> 8, rem = t & 255, rg = rem >> 6, c = rem & 63;
        int base = h ? baseR : baseL;
        float part = 0.0f;
        #pragma unroll 10
        for (int j = rg; j < NN; j += 4) part += g_msg[(size_t)(base + j) * 64 + c];
        sp[t] = part;
    }
    __syncthreads();
    if (t < 128) {
        int b0 = (t >> 6) * 256, o = t & 63;
        msum[t] = sp[b0 + o] + sp[b0 + 64 + o] + sp[b0 + 128 + o] + sp[b0 + 192 + o];
    }
    __syncthreads();
    if (t < 128) {
        int hh = t >> 6, o = t & 63;
        float acc = 0.0f;
        #pragma unroll 16
        for (int i = 0; i < 64; i++) acc += msum[hh * 64 + i] * gcn_w[i * 64 + o];
        acc += (float)NN * (gcn_wb[o] + gcn_b[o]);
        x[t] = tanhf(acc / (hh ? degR : degL));
    }
    __syncthreads();
}

// ---------------- support encoder row: x(sm+640) -> y(global)
__device__ __forceinline__ void supp_row(float* __restrict__ y,
        const float* __restrict__ w1, const float* __restrict__ b1,
        const float* __restrict__ w2, const float* __restrict__ b2,
        const float* __restrict__ lg, const float* __restrict__ lb,
        float* sm, int t) {
    float* x  = sm + 640;    // 128
    float* sa = sm + 768;    // 256
    float* sh = sm + 1024;   // 128
    float* sr = sm + 1152;   // 64
    float* sc = sm + 1216;   // 2
    if (t < DI) {
        float a = b1[t];
        #pragma unroll 16
        for (int j = 0; j < DM; j++) a += x[j] * w1[j * DI + t];
        sa[t] = fmaxf(a, 0.0f);
    }
    __syncthreads();
    if (t < DM) {
        float h = b2[t] + x[t];
        #pragma unroll 16
        for (int j = 0; j < DI; j++) h += sa[j] * w2[j * DM + t];
        sh[t] = h;
    }
    __syncthreads();
    if (t < 64) sr[t] = sh[t] + sh[t + 64];
    __syncthreads();
    if (t < 32) {
        float v = sr[t] + sr[t + 32];
        for (int o = 16; o; o >>= 1) v += __shfl_down_sync(0xffffffff, v, o);
        if (t == 0) sc[0] = v / (float)DM;
    }
    __syncthreads();
    float mu = sc[0];
    if (t < 64) {
        float d0 = sh[t] - mu, d1 = sh[t + 64] - mu;
        sr[t] = d0 * d0 + d1 * d1;
    }
    __syncthreads();
    if (t < 32) {
        float v = sr[t] + sr[t + 32];
        for (int o = 16; o; o >>= 1) v += __shfl_down_sync(0xffffffff, v, o);
        if (t == 0) sc[1] = sqrtf(v / (float)(DM - 1));
    }
    __syncthreads();
    if (t < DM) y[t] = (sh[t] - mu) / (sc[1] + LN_EPS) * lg[t] + lb[t];
    __syncthreads();
}

// ---------------- in-block 4-row GEMM vs 1024-col weight (K=128, k-split halves) ----------------
// XPROJ: out -> SXP, += bih+bhh.  else: out -> SPART, += SXP + attn@SW (rank-5 correction)
template<bool XPROJ>
__device__ __forceinline__ void gemm4(float* sm, const float* __restrict__ Bmat,
        const float* __restrict__ bih, const float* __restrict__ bhh, int t) {
    int kh = t >> 8, u = t & 255, c4 = u * 4;
    const float* Bp = Bmat + (size_t)(kh * 64) * 1024 + c4;
    const float* Ap = sm + SHT + kh * 64 * 4;
    unsigned long long acc[8];
    #pragma unroll
    for (int i = 0; i < 8; i++) acc[i] = 0ULL;
    #pragma unroll 8
    for (int k = 0; k < 64; k++) {
        float4 a4 = *(const float4*)(Ap + k * 4);
        ulonglong2 bv = *(const ulonglong2*)(Bp + (size_t)k * 1024);
        unsigned long long ar;
        FPACK2(ar, a4.x); FMA2(acc[0], bv.x, ar); FMA2(acc[1], bv.y, ar);
        FPACK2(ar, a4.y); FMA2(acc[2], bv.x, ar); FMA2(acc[3], bv.y, ar);
        FPACK2(ar, a4.z); FMA2(acc[4], bv.x, ar); FMA2(acc[5], bv.y, ar);
        FPACK2(ar, a4.w); FMA2(acc[6], bv.x, ar); FMA2(acc[7], bv.y, ar);
    }
    if (kh == 1) {
        #pragma unroll
        for (int r = 0; r < 4; r++) {
            float o0, o1, o2, o3;
            UNPACK2(o0, o1, acc[r*2]); UNPACK2(o2, o3, acc[r*2+1]);
            *(float4*)&sm[SPART + r * 1024 + c4] = make_float4(o0, o1, o2, o3);
        }
    }
    __syncthreads();
    if (kh == 0) {
        float4 sw[FEW];
        float4 bb;
        if (XPROJ) {
            bb = make_float4(bih[c4]+bhh[c4], bih[c4+1]+bhh[c4+1],
                             bih[c4+2]+bhh[c4+2], bih[c4+3]+bhh[c4+3]);
        } else {
            #pragma unroll
            for (int j = 0; j < FEW; j++) sw[j] = *(const float4*)&g_SW[j * 1024 + c4];
        }
        #pragma unroll
        for (int r = 0; r < 4; r++) {
            float o0, o1, o2, o3;
            UNPACK2(o0, o1, acc[r*2]); UNPACK2(o2, o3, acc[r*2+1]);
            float4 pv = *(const float4*)&sm[SPART + r * 1024 + c4];
            o0 += pv.x; o1 += pv.y; o2 += pv.z; o3 += pv.w;
            if (XPROJ) {
                o0 += bb.x; o1 += bb.y; o2 += bb.z; o3 += bb.w;
                *(float4*)&sm[SXP + r * 1024 + c4] = make_float4(o0, o1, o2, o3);
            } else {
                float4 xv = *(const float4*)&sm[SXP + r * 1024 + c4];
                o0 += xv.x; o1 += xv.y; o2 += xv.z; o3 += xv.w;
                #pragma unroll
                for (int j = 0; j < FEW; j++) {
                    float aj = sm[SATT + r * 8 + j];
                    o0 += aj * sw[j].x; o1 += aj * sw[j].y;
                    o2 += aj * sw[j].z; o3 += aj * sw[j].w;
                }
                *(float4*)&sm[SPART + r * 1024 + c4] = make_float4(o0, o1, o2, o3);
            }
        }
    }
    __syncthreads();
}

// ---------------- LSTM elementwise + attention for 4 rows, fully in-block ----------------
__device__ __forceinline__ void elt4(float* sm, const float* gbase, float& c0, float& c1,
                                     int t, int row0, int last, float* __restrict__ out) {
    int r = t >> 7, u = t & 127, u2 = u * 2;
    const float* gp = gbase + r * 1024;
    float gi0 = gp[u2],       gi1 = gp[u2 + 1];
    float gf0 = gp[256 + u2], gf1 = gp[257 + u2];
    float gg0 = gp[512 + u2], gg1 = gp[513 + u2];
    float go0 = gp[768 + u2], go1 = gp[769 + u2];
    c0 = sigmoidf_(gf0) * c0 + sigmoidf_(gi0) * tanhf(gg0);
    c1 = sigmoidf_(gf1) * c1 + sigmoidf_(gi1) * tanhf(gg1);
    if (u2 < 128) {
        float h0 = sm[SQ + r * 128 + u2]     + sigmoidf_(go0) * tanhf(c0);
        float h1 = sm[SQ + r * 128 + u2 + 1] + sigmoidf_(go1) * tanhf(c1);
        sm[SHT + u2 * 4 + r]       = h0;
        sm[SHT + (u2 + 1) * 4 + r] = h1;
    }
    __syncthreads();
    float hv = sm[SHT + u * 4 + r];
    int lane = t & 31, wid = t >> 5;
    #pragma unroll
    for (int j = 0; j < FEW; j++) {
        float p = hv * sm[SSUP + j * 128 + u];
        for (int o = 16; o; o >>= 1) p += __shfl_down_sync(0xffffffff, p, o);
        if (lane == 0) sm[SRED + wid] = p;
        __syncthreads();
        if (t < 4) sm[SLOG + t * 8 + j] = sm[SRED + 4*t] + sm[SRED + 4*t + 1]
                                        + sm[SRED + 4*t + 2] + sm[SRED + 4*t + 3];
        __syncthreads();
    }
    if (last) {
        if (t < 4) {
            #pragma unroll
            for (int j = 0; j < FEW; j++) out[(row0 + t) * FEW + j] = sm[SLOG + t * 8 + j];
        }
        return;
    }
    if (t < 4) {
        float mx = sm[SLOG + t * 8];
        #pragma unroll
        for (int j = 1; j < FEW; j++) mx = fmaxf(mx, sm[SLOG + t * 8 + j]);
        float s = 0.0f, e[FEW];
        #pragma unroll
        for (int j = 0; j < FEW; j++) { e[j] = expf(sm[SLOG + t * 8 + j] - mx); s += e[j]; }
        #pragma unroll
        for (int j = 0; j < FEW; j++) sm[SATT + t * 8 + j] = e[j] / s;
    }
    __syncthreads();
}

// ---------------- THE kernel ----------------
__global__ __launch_bounds__(NT, 1) void mega_kernel(
        const int2* __restrict__ ql, const int2* __restrict__ qr,
        const int2* __restrict__ sl, const int2* __restrict__ sr,
        const float* __restrict__ qld, const float* __restrict__ qrd,
        const float* __restrict__ sld, const float* __restrict__ srd,
        const float* __restrict__ ent_emb, const float* __restrict__ rel_mat,
        const float* __restrict__ gcn_w, const float* __restrict__ gcn_wb, const float* __restrict__ gcn_b,
        const float* __restrict__ w1, const float* __restrict__ b1,
        const float* __restrict__ w2, const float* __restrict__ b2,
        const float* __restrict__ lg, const float* __restrict__ lb,
        const float* __restrict__ wih, const float* __restrict__ whh,
        const float* __restrict__ bih, const float* __restrict__ bhh,
        float* __restrict__ out) {
    __shared__ __align__(16) float smem[10240];   // 40KB union
    __shared__ unsigned long long s_base;
    __shared__ int s_r;
    int t = threadIdx.x, bid = blockIdx.x;
    if (t == 0) {
        unsigned long long c;
        asm volatile("ld.global.acquire.gpu.u64 %0, [%1];" : "=l"(c) : "l"(&g_barcnt) : "memory");
        s_base = (c / (unsigned long long)(GRID * NBAR)) * (unsigned long long)(GRID * NBAR);
    }
    __syncthreads();
    unsigned long long bbase = s_base;

    // ===== Stage 0: scatter into padded per-rel bins; reset work queue =====
    if (bid == 0 && t == 0) g_relctr = 0;
    {
        int lo = bid * SCHUNK, hi = min(lo + SCHUNK, NPTOT);
        for (int idx = lo + t; idx < hi; idx += NT) {
            int2 c;
            if (idx < NPQ)                 c = ql[idx];
            else if (idx < 2*NPQ)          c = qr[idx - NPQ];
            else if (idx < 2*NPQ + NPS)    c = sl[idx - 2*NPQ];
            else                           c = sr[idx - 2*NPQ - NPS];
            int pos = atomicAdd(&g_cnt[c.x], 1);
            if (pos < CAP) g_pairs[c.x * CAP + pos] = make_int2(idx, c.y);
        }
    }
    grid_bar(bbase, 0);

    // ===== Stage 1: binned RESCAL matvecs, dynamic rel scheduling =====
    {
        float* sR   = smem;                  // 64*68 = 4352
        float* sE01 = smem + 4352;           // 16*128
        float* sE23 = smem + 6400;           // 16*128
        int w = t >> 5, lane = t & 31;
        for (;;) {
            if (t == 0) s_r = atomicAdd(&g_relctr, 1);
            __syncthreads();
            int r = s_r;
            if (r >= NRELS) break;
            int cnt = g_cnt[r];
            __syncthreads();
            if (t == 0) g_cnt[r] = 0;
            if (cnt > 0) {
                if (cnt > CAP) cnt = CAP;
                const float* R = rel_mat + (size_t)r * 4096;
                for (int i = t; i < 4096; i += NT) sR[(i >> 6) * 68 + (i & 63)] = R[i];
                __syncthreads();
                float* e01 = sE01 + w * 128;
                float* e23 = sE23 + w * 128;
                for (int base = w * 4; base < cnt; base += 64) {
                    int np = min(4, cnt - base);
                    int origs[4];
                    #pragma unroll
                    for (int p = 0; p < 4; p++) {
                        if (p < np) {
                            int2 pr = g_pairs[r * CAP + base + p];
                            origs[p] = pr.x;
                            float2 v = ((const float2*)(ent_emb + (size_t)pr.y * 64))[lane];
                            float* dstE = (p < 2) ? e01 : e23;
                            int pp = p & 1;
                            dstE[4*lane + pp]     = v.x;
                            dstE[4*lane + 2 + pp] = v.y;
                        }
                    }
                    __syncwarp();
                    unsigned long long aA01=0, aA23=0, aB01=0, aB23=0;
                    #pragma unroll
                    for (int j4 = 0; j4 < 64; j4 += 4) {
                        float4 rA = *(const float4*)&sR[lane * 68 + j4];
                        float4 rB = *(const float4*)&sR[(lane + 32) * 68 + j4];
                        ulonglong2 E01a = *(const ulonglong2*)(e01 + j4*2);
                        ulonglong2 E01b = *(const ulonglong2*)(e01 + j4*2 + 4);
                        ulonglong2 E23a = *(const ulonglong2*)(e23 + j4*2);
                        ulonglong2 E23b = *(const ulonglong2*)(e23 + j4*2 + 4);
                        unsigned long long dA, dB;
                        FPACK2(dA, rA.x); FPACK2(dB, rB.x);
                        FMA2(aA01, E01a.x, dA); FMA2(aA23, E23a.x, dA);
                        FMA2(aB01, E01a.x, dB); FMA2(aB23, E23a.x, dB);
                        FPACK2(dA, rA.y); FPACK2(dB, rB.y);
                        FMA2(aA01, E01a.y, dA); FMA2(aA23, E23a.y, dA);
                        FMA2(aB01, E01a.y, dB); FMA2(aB23, E23a.y, dB);
                        FPACK2(dA, rA.z); FPACK2(dB, rB.z);
                        FMA2(aA01, E01b.x, dA); FMA2(aA23, E23b.x, dA);
                        FMA2(aB01, E01b.x, dB); FMA2(aB23, E23b.x, dB);
                        FPACK2(dA, rA.w); FPACK2(dB, rB.w);
                        FMA2(aA01, E01b.y, dA); FMA2(aA23, E23b.y, dA);
                        FMA2(aB01, E01b.y, dB); FMA2(aB23, E23b.y, dB);
                    }
                    float accA[4], accB[4];
                    UNPACK2(accA[0], accA[1], aA01); UNPACK2(accA[2], accA[3], aA23);
                    UNPACK2(accB[0], accB[1], aB01); UNPACK2(accB[2], accB[3], aB23);
                    #pragma unroll
                    for (int p = 0; p < 4; p++) {
                        if (p < np) {
                            float* dst = g_msg + (size_t)origs[p] * 64;
                            dst[lane]      = accA[p];
                            dst[lane + 32] = accB[p];
                        }
                    }
                    __syncwarp();
                }
            }
            __syncthreads();   // sR/sE reuse + s_r rewrite safety
        }
    }
    grid_bar(bbase, 1);

    // ===== Stage 2: gcn finalize + support encoder, fused per row =====
    if (bid < Bq) {
        gcn_row(bid * NN, NPQ + bid * NN, qld[bid], qrd[bid], gcn_w, gcn_wb, gcn_b, smem, t);
        supp_row(g_query_g + bid * DM, w1, b1, w2, b2, lg, lb, smem, t);
    } else if (bid < Bq + FEW) {
        int s = bid - Bq;
        gcn_row(2*NPQ + s * NN, 2*NPQ + NPS + s * NN, sld[s], srd[s], gcn_w, gcn_wb, gcn_b, smem, t);
        supp_row(g_support_g + s * DM, w1, b1, w2, b2, lg, lb, smem, t);
    }
    grid_bar(bbase, 2);

    // ===== Stage 3: blocks 0-31: xproj + LSTM step 0; blocks 32-47: SW =====
    int row0 = bid * 4;
    float c0 = 0.0f, c1 = 0.0f;
    if (bid < 32) {
        {   // load query_g rows (transposed + plain) and support_g into smem
            int r = t >> 7, k = t & 127;
            float v = g_query_g[(size_t)(row0 + r) * 128 + k];
            smem[SHT + k * 4 + r] = v;
            smem[SQ + r * 128 + k] = v;
            for (int i = t; i < FEW * 128; i += NT) smem[SSUP + i] = g_support_g[i];
        }
        __syncthreads();
        gemm4<true>(smem, wih, bih, bhh, t);
        elt4(smem, smem + SXP, c0, c1, t, row0, 0, out);
    } else if (bid < 48) {
        int cb = bid - 32;   // 0..15
        if (t < 320) {
            int j = t >> 6, col = cb * 64 + (t & 63);
            float acc = 0.0f;
            #pragma unroll 8
            for (int k = 0; k < 128; k++)
                acc += g_support_g[j * 128 + k] * whh[(size_t)(128 + k) * 1024 + col];
            g_SW[j * 1024 + col] = acc;
        }
    }
    grid_bar(bbase, 3);

    // ===== LSTM steps 1..3: fully intra-block, no grid barriers =====
    if (bid < 32) {
        #pragma unroll
        for (int s = 1; s < 4; s++) {
            gemm4<false>(smem, whh, nullptr, nullptr, t);
            elt4(smem, smem + SPART, c0, c1, t, row0, (s == 3) ? 1 : 0, out);
        }
    }
}

// ---------------- host ----------------
extern "C" void kernel_launch(void* const* d_in, const int* in_sizes, int n_in,
                              void* d_out, int out_size) {
    const int2*  ql     = (const int2*)d_in[0];
    const int2*  qr     = (const int2*)d_in[1];
    const int2*  sl     = (const int2*)d_in[2];
    const int2*  sr     = (const int2*)d_in[3];
    const float* qld    = (const float*)d_in[4];
    const float* qrd    = (const float*)d_in[5];
    const float* sld    = (const float*)d_in[6];
    const float* srd    = (const float*)d_in[7];
    const float* ent    = (const float*)d_in[8];
    const float* relm   = (const float*)d_in[9];
    const float* gcn_w  = (const float*)d_in[10];
    const float* gcn_wb = (const float*)d_in[11];
    const float* gcn_b  = (const float*)d_in[12];
    const float* se_w1  = (const float*)d_in[13];
    const float* se_b1  = (const float*)d_in[14];
    const float* se_w2  = (const float*)d_in[15];
    const float* se_b2  = (const float*)d_in[16];
    const float* ln_g   = (const float*)d_in[17];
    const float* ln_b   = (const float*)d_in[18];
    const float* wih    = (const float*)d_in[19];
    const float* whh    = (const float*)d_in[20];
    const float* bih    = (const float*)d_in[21];
    const float* bhh    = (const float*)d_in[22];
    float* out = (float*)d_out;

    mega_kernel<<<GRID, NT>>>(ql, qr, sl, sr, qld, qrd, sld, srd, ent, relm,
                              gcn_w, gcn_wb, gcn_b, se_w1, se_b1, se_w2, se_b2,
                              ln_g, ln_b, wih, whh, bih, bhh, out);
}

// round 8
// speedup vs baseline: 2.1060x; 1.1188x over previous
#include <cuda_runtime.h>
#include <math.h>
#include <stdint.h>

#define Dd 64
#define DM 128
#define DI 256
#define Bq 128
#define NN 200
#define FEW 5
#define NRELS 500
#define NPQ (Bq*NN)
#define NPS (FEW*NN)
#define NPTOT (2*NPQ + 2*NPS)   // 53200
#define CAP 512
#define LN_EPS 0.001f
#define GRID 148
#define NT 512
#define TOTBAR (3ULL * GRID)    // per replay: k1 uses 1 barrier, k2 uses 2
#define SCHUNK 360

// k2 smem layout (float offsets) — packed 512-col gates
#define SXP   0       // 2048  xproj 4x512 (packed i|f|g|o)
#define SP1   2048    // 2048  partial kh=1 / final gates
#define SP2   4096    // 2048  partial kh=2
#define SP3   6144    // 2048  partial kh=3
#define SHT   8192    // 512   h transposed [128][4]
#define SQ    8704    // 512   query_g rows [4][128]
#define SSUP  9216    // 640   support_g [5][128]
#define SLOG  9856    // 32
#define SATT  9888    // 32
#define SRED  9920    // 16

// ---------------- device scratch ----------------
__device__ int   g_cnt[512];                 // zero-init; self-zeroed each pass
__device__ int2  g_pairs[NRELS*CAP + 8];     // +8 pad for unconditional group loads
__device__ float g_msg[(size_t)NPTOT*64];
__device__ float g_query_g[Bq*DM];
__device__ float g_support_g[FEW*DM];
__device__ float g_SW[FEW*512];              // packed: support_g @ whh[128:], useful cols
__device__ int   g_relctr;
__device__ unsigned long long g_barcnt;      // monotonic, never reset

__device__ __forceinline__ float sigmoidf_(float x) { return 1.0f / (1.0f + expf(-x)); }

// packed fp32x2 helpers (Blackwell FFMA2)
#define FPACK2(d, f)      asm("mov.b64 %0, {%1, %1};" : "=l"(d) : "f"(f))
#define FMA2(acc, e, r)   asm("fma.rn.f32x2 %0, %1, %2, %3;" : "=l"(acc) : "l"(e), "l"(r), "l"(acc))
#define UNPACK2(lo, hi, v) asm("mov.b64 {%0, %1}, %2;" : "=f"(lo), "=f"(hi) : "l"(v))

__device__ __forceinline__ unsigned long long bar_read() {
    unsigned long long v;
    asm volatile("ld.global.acquire.gpu.u64 %0, [%1];" : "=l"(v) : "l"(&g_barcnt) : "memory");
    return v;
}
// k = global barrier index within this replay (0 for k1; 1,2 for k2)
__device__ __forceinline__ void grid_bar(unsigned long long base, int k) {
    __syncthreads();
    if (threadIdx.x == 0) {
        __threadfence();
        atomicAdd(&g_barcnt, 1ULL);
        unsigned long long target = base + (unsigned long long)GRID * (unsigned long long)(k + 1);
        while (bar_read() < target) {}
        __threadfence();
    }
    __syncthreads();
}
__device__ __forceinline__ unsigned long long epoch_base() {
    return (bar_read() / TOTBAR) * TOTBAR;
}

// ================= KERNEL 1: scatter + binned RESCAL =================
__global__ __launch_bounds__(NT, 1) void k1_scatter_rescal(
        const int2* __restrict__ ql, const int2* __restrict__ qr,
        const int2* __restrict__ sl, const int2* __restrict__ sr,
        const float* __restrict__ ent_emb, const float* __restrict__ rel_mat) {
    __shared__ __align__(16) float smem[8448];
    __shared__ unsigned long long s_base;
    __shared__ int s_r;
    int t = threadIdx.x, bid = blockIdx.x;
    if (t == 0) s_base = epoch_base();
    __syncthreads();
    unsigned long long bbase = s_base;

    // ---- scatter into padded per-rel bins; reset work queue ----
    if (bid == 0 && t == 0) g_relctr = 0;
    {
        int lo = bid * SCHUNK, hi = min(lo + SCHUNK, NPTOT);
        for (int idx = lo + t; idx < hi; idx += NT) {
            int2 c;
            if (idx < NPQ)                 c = ql[idx];
            else if (idx < 2*NPQ)          c = qr[idx - NPQ];
            else if (idx < 2*NPQ + NPS)    c = sl[idx - 2*NPQ];
            else                           c = sr[idx - 2*NPQ - NPS];
            int pos = atomicAdd(&g_cnt[c.x], 1);
            if (pos < CAP) g_pairs[c.x * CAP + pos] = make_int2(idx, c.y);
        }
    }
    grid_bar(bbase, 0);

    // ---- binned RESCAL matvecs, dynamic rel queue, branch-free prefetch ----
    {
        float* sR   = smem;                  // 64*68 = 4352
        float* sE01 = smem + 4352;           // 16*128
        float* sE23 = smem + 6400;           // 16*128
        int w = t >> 5, lane = t & 31;
        for (;;) {
            if (t == 0) s_r = atomicAdd(&g_relctr, 1);
            __syncthreads();
            int r = s_r;
            if (r >= NRELS) break;
            int cnt = g_cnt[r];
            __syncthreads();
            if (t == 0) g_cnt[r] = 0;
            if (cnt > 0) {
                if (cnt > CAP) cnt = CAP;
                const float* R = rel_mat + (size_t)r * 4096;
                for (int i = t; i < 4096; i += NT) sR[(i >> 6) * 68 + (i & 63)] = R[i];
                __syncthreads();
                float* e01 = sE01 + w * 128;
                float* e23 = sE23 + w * 128;
                for (int base = w * 4; base < cnt; base += 64) {
                    int np = min(4, cnt - base);
                    // unconditional loads (bins padded; stale idx are valid entities)
                    int2 pr[4];
                    float2 ev[4];
                    #pragma unroll
                    for (int p = 0; p < 4; p++) pr[p] = g_pairs[r * CAP + base + p];
                    #pragma unroll
                    for (int p = 0; p < 4; p++)
                        ev[p] = ((const float2*)(ent_emb + (size_t)pr[p].y * 64))[lane];
                    #pragma unroll
                    for (int p = 0; p < 4; p++) {
                        float* dstE = (p < 2) ? e01 : e23;
                        int pp = p & 1;
                        dstE[4*lane + pp]     = ev[p].x;
                        dstE[4*lane + 2 + pp] = ev[p].y;
                    }
                    __syncwarp();
                    unsigned long long aA01=0, aA23=0, aB01=0, aB23=0;
                    #pragma unroll
                    for (int j4 = 0; j4 < 64; j4 += 4) {
                        float4 rA = *(const float4*)&sR[lane * 68 + j4];
                        float4 rB = *(const float4*)&sR[(lane + 32) * 68 + j4];
                        ulonglong2 E01a = *(const ulonglong2*)(e01 + j4*2);
                        ulonglong2 E01b = *(const ulonglong2*)(e01 + j4*2 + 4);
                        ulonglong2 E23a = *(const ulonglong2*)(e23 + j4*2);
                        ulonglong2 E23b = *(const ulonglong2*)(e23 + j4*2 + 4);
                        unsigned long long dA, dB;
                        FPACK2(dA, rA.x); FPACK2(dB, rB.x);
                        FMA2(aA01, E01a.x, dA); FMA2(aA23, E23a.x, dA);
                        FMA2(aB01, E01a.x, dB); FMA2(aB23, E23a.x, dB);
                        FPACK2(dA, rA.y); FPACK2(dB, rB.y);
                        FMA2(aA01, E01a.y, dA); FMA2(aA23, E23a.y, dA);
                        FMA2(aB01, E01a.y, dB); FMA2(aB23, E23a.y, dB);
                        FPACK2(dA, rA.z); FPACK2(dB, rB.z);
                        FMA2(aA01, E01b.x, dA); FMA2(aA23, E23b.x, dA);
                        FMA2(aB01, E01b.x, dB); FMA2(aB23, E23b.x, dB);
                        FPACK2(dA, rA.w); FPACK2(dB, rB.w);
                        FMA2(aA01, E01b.y, dA); FMA2(aA23, E23b.y, dA);
                        FMA2(aB01, E01b.y, dB); FMA2(aB23, E23b.y, dB);
                    }
                    float accA[4], accB[4];
                    UNPACK2(accA[0], accA[1], aA01); UNPACK2(accA[2], accA[3], aA23);
                    UNPACK2(accB[0], accB[1], aB01); UNPACK2(accB[2], accB[3], aB23);
                    #pragma unroll
                    for (int p = 0; p < 4; p++) {
                        if (p < np) {
                            float* dst = g_msg + (size_t)pr[p].x * 64;
                            dst[lane]      = accA[p];
                            dst[lane + 32] = accB[p];
                        }
                    }
                    __syncwarp();
                }
            }
            __syncthreads();
        }
    }
}

// ---------------- gcn row (512 threads) ----------------
__device__ __forceinline__ void gcn_row(int baseL, int baseR, float degL, float degR,
        const float* __restrict__ gcn_w, const float* __restrict__ gcn_wb, const float* __restrict__ gcn_b,
        float* sm, int t) {
    float* sp   = sm;          // 512
    float* msum = sm + 512;    // 128
    float* x    = sm + 640;    // 128
    {
        int h = t >> 8, rem = t & 255, rg = rem >> 6, c = rem & 63;
        int base = h ? baseR : baseL;
        float part = 0.0f;
        #pragma unroll 10
        for (int j = rg; j < NN; j += 4) part += g_msg[(size_t)(base + j) * 64 + c];
        sp[t] = part;
    }
    __syncthreads();
    if (t < 128) {
        int b0 = (t >> 6) * 256, o = t & 63;
        msum[t] = sp[b0 + o] + sp[b0 + 64 + o] + sp[b0 + 128 + o] + sp[b0 + 192 + o];
    }
    __syncthreads();
    if (t < 128) {
        int hh = t >> 6, o = t & 63;
        float acc = 0.0f;
        #pragma unroll 16
        for (int i = 0; i < 64; i++) acc += msum[hh * 64 + i] * gcn_w[i * 64 + o];
        acc += (float)NN * (gcn_wb[o] + gcn_b[o]);
        x[t] = tanhf(acc / (hh ? degR : degL));
    }
    __syncthreads();
}

// ---------------- support encoder row: x(sm+640) -> y(global) ----------------
__device__ __forceinline__ void supp_row(float* __restrict__ y,
        const float* __restrict__ w1, const float* __restrict__ b1,
        const float* __restrict__ w2, const float* __restrict__ b2,
        const float* __restrict__ lg, const float* __restrict__ lb,
        float* sm, int t) {
    float* x  = sm + 640;    // 128
    float* sa = sm + 768;    // 256
    float* sh = sm + 1024;   // 128
    float* sr = sm + 1152;   // 64
    float* sc = sm + 1216;   // 2
    if (t < DI) {
        float a = b1[t];
        #pragma unroll 16
        for (int j = 0; j < DM; j++) a += x[j] * w1[j * DI + t];
        sa[t] = fmaxf(a, 0.0f);
    }
    __syncthreads();
    if (t < DM) {
        float h = b2[t] + x[t];
        #pragma unroll 16
        for (int j = 0; j < DI; j++) h += sa[j] * w2[j * DM + t];
        sh[t] = h;
    }
    __syncthreads();
    if (t < 64) sr[t] = sh[t] + sh[t + 64];
    __syncthreads();
    if (t < 32) {
        float v = sr[t] + sr[t + 32];
        for (int o = 16; o; o >>= 1) v += __shfl_down_sync(0xffffffff, v, o);
        if (t == 0) sc[0] = v / (float)DM;
    }
    __syncthreads();
    float mu = sc[0];
    if (t < 64) {
        float d0 = sh[t] - mu, d1 = sh[t + 64] - mu;
        sr[t] = d0 * d0 + d1 * d1;
    }
    __syncthreads();
    if (t < 32) {
        float v = sr[t] + sr[t + 32];
        for (int o = 16; o; o >>= 1) v += __shfl_down_sync(0xffffffff, v, o);
        if (t == 0) sc[1] = sqrtf(v / (float)(DM - 1));
    }
    __syncthreads();
    if (t < DM) y[t] = (sh[t] - mu) / (sc[1] + LN_EPS) * lg[t] + lb[t];
    __syncthreads();
}

// ---------------- packed 4-row GEMM: (4x128) @ (128 x packed512), 4-way K-split ----------------
// packed col c -> orig col (c>>7)*256 + (c&127)  [gate chunks i|f|g|o, first 128 cols each]
// XPROJ: out->SXP, +=bih+bhh.  else: out->SP1(gates), += SXP + attn@SW(packed)
template<bool XPROJ>
__device__ __forceinline__ void gemm4p(float* sm, const float* __restrict__ Bmat,
        const float* __restrict__ bih, const float* __restrict__ bhh, int t) {
    int kh = t >> 7, u = t & 127;
    int c4p = u * 4;
    int gate = c4p >> 7;
    int colo = gate * 256 + (c4p & 127);
    const float* Bp = Bmat + (size_t)(kh * 32) * 1024 + colo;
    const float* Ap = sm + SHT + kh * 32 * 4;
    unsigned long long acc[8];
    #pragma unroll
    for (int i = 0; i < 8; i++) acc[i] = 0ULL;
    #pragma unroll 8
    for (int k = 0; k < 32; k++) {
        float4 a4 = *(const float4*)(Ap + k * 4);           // broadcast (4 rows at k)
        ulonglong2 bv = *(const ulonglong2*)(Bp + (size_t)k * 1024);
        unsigned long long ar;
        FPACK2(ar, a4.x); FMA2(acc[0], bv.x, ar); FMA2(acc[1], bv.y, ar);
        FPACK2(ar, a4.y); FMA2(acc[2], bv.x, ar); FMA2(acc[3], bv.y, ar);
        FPACK2(ar, a4.z); FMA2(acc[4], bv.x, ar); FMA2(acc[5], bv.y, ar);
        FPACK2(ar, a4.w); FMA2(acc[6], bv.x, ar); FMA2(acc[7], bv.y, ar);
    }
    if (kh) {
        float* pdst = sm + SP1 + (kh - 1) * 2048;
        #pragma unroll
        for (int r = 0; r < 4; r++) {
            float o0, o1, o2, o3;
            UNPACK2(o0, o1, acc[r*2]); UNPACK2(o2, o3, acc[r*2+1]);
            *(float4*)&pdst[r * 512 + c4p] = make_float4(o0, o1, o2, o3);
        }
    }
    __syncthreads();
    if (kh == 0) {
        float4 sw[FEW];
        float4 bb;
        if (XPROJ) {
            bb = make_float4(bih[colo]+bhh[colo], bih[colo+1]+bhh[colo+1],
                             bih[colo+2]+bhh[colo+2], bih[colo+3]+bhh[colo+3]);
        } else {
            #pragma unroll
            for (int j = 0; j < FEW; j++) sw[j] = *(const float4*)&g_SW[j * 512 + c4p];
        }
        #pragma unroll
        for (int r = 0; r < 4; r++) {
            float o0, o1, o2, o3;
            UNPACK2(o0, o1, acc[r*2]); UNPACK2(o2, o3, acc[r*2+1]);
            float4 p1 = *(const float4*)&sm[SP1 + r * 512 + c4p];
            float4 p2 = *(const float4*)&sm[SP2 + r * 512 + c4p];
            float4 p3 = *(const float4*)&sm[SP3 + r * 512 + c4p];
            o0 += p1.x + p2.x + p3.x; o1 += p1.y + p2.y + p3.y;
            o2 += p1.z + p2.z + p3.z; o3 += p1.w + p2.w + p3.w;
            if (XPROJ) {
                o0 += bb.x; o1 += bb.y; o2 += bb.z; o3 += bb.w;
                *(float4*)&sm[SXP + r * 512 + c4p] = make_float4(o0, o1, o2, o3);
            } else {
                float4 xv = *(const float4*)&sm[SXP + r * 512 + c4p];
                o0 += xv.x; o1 += xv.y; o2 += xv.z; o3 += xv.w;
                #pragma unroll
                for (int j = 0; j < FEW; j++) {
                    float aj = sm[SATT + r * 8 + j];
                    o0 += aj * sw[j].x; o1 += aj * sw[j].y;
                    o2 += aj * sw[j].z; o3 += aj * sw[j].w;
                }
                *(float4*)&sm[SP1 + r * 512 + c4p] = make_float4(o0, o1, o2, o3);
            }
        }
    }
    __syncthreads();
}

// ---------------- LSTM elementwise + attention, packed gates (smem), c width 128 ----------------
__device__ __forceinline__ void elt4p(float* sm, const float* __restrict__ gp_base,
                                      float& c, int t, int row0, int last, float* __restrict__ out) {
    int r = t >> 7, u = t & 127;
    const float* gp = gp_base + r * 512;
    float gi = gp[u], gf = gp[128 + u], gg = gp[256 + u], go = gp[384 + u];
    c = sigmoidf_(gf) * c + sigmoidf_(gi) * tanhf(gg);
    float h = sm[SQ + r * 128 + u] + sigmoidf_(go) * tanhf(c);
    sm[SHT + u * 4 + r] = h;
    __syncthreads();
    int lane = t & 31, wid = t >> 5;
    #pragma unroll
    for (int j = 0; j < FEW; j++) {
        float p = h * sm[SSUP + j * 128 + u];
        for (int o = 16; o; o >>= 1) p += __shfl_down_sync(0xffffffff, p, o);
        if (lane == 0) sm[SRED + wid] = p;
        __syncthreads();
        if (t < 4) sm[SLOG + t * 8 + j] = sm[SRED + 4*t] + sm[SRED + 4*t + 1]
                                        + sm[SRED + 4*t + 2] + sm[SRED + 4*t + 3];
        __syncthreads();
    }
    if (last) {
        if (t < 4) {
            #pragma unroll
            for (int j = 0; j < FEW; j++) out[(row0 + t) * FEW + j] = sm[SLOG + t * 8 + j];
        }
        return;
    }
    if (t < 4) {
        float mx = sm[SLOG + t * 8];
        #pragma unroll
        for (int j = 1; j < FEW; j++) mx = fmaxf(mx, sm[SLOG + t * 8 + j]);
        float s = 0.0f, e[FEW];
        #pragma unroll
        for (int j = 0; j < FEW; j++) { e[j] = expf(sm[SLOG + t * 8 + j] - mx); s += e[j]; }
        #pragma unroll
        for (int j = 0; j < FEW; j++) sm[SATT + t * 8 + j] = e[j] / s;
    }
    __syncthreads();
}

// ================= KERNEL 2: gcn/supp + LSTM tail =================
__global__ __launch_bounds__(NT, 1) void k2_tail(
        const float* __restrict__ qld, const float* __restrict__ qrd,
        const float* __restrict__ sld, const float* __restrict__ srd,
        const float* __restrict__ gcn_w, const float* __restrict__ gcn_wb, const float* __restrict__ gcn_b,
        const float* __restrict__ w1, const float* __restrict__ b1,
        const float* __restrict__ w2, const float* __restrict__ b2,
        const float* __restrict__ lg, const float* __restrict__ lb,
        const float* __restrict__ wih, const float* __restrict__ whh,
        const float* __restrict__ bih, const float* __restrict__ bhh,
        float* __restrict__ out) {
    __shared__ __align__(16) float smem[9984];   // 39KB union
    __shared__ unsigned long long s_base;
    int t = threadIdx.x, bid = blockIdx.x;
    if (t == 0) s_base = epoch_base();
    __syncthreads();
    unsigned long long bbase = s_base;

    // ---- Stage A: gcn finalize + support encoder ----
    if (bid < Bq) {
        gcn_row(bid * NN, NPQ + bid * NN, qld[bid], qrd[bid], gcn_w, gcn_wb, gcn_b, smem, t);
        supp_row(g_query_g + bid * DM, w1, b1, w2, b2, lg, lb, smem, t);
    } else if (bid < Bq + FEW) {
        int s = bid - Bq;
        gcn_row(2*NPQ + s * NN, 2*NPQ + NPS + s * NN, sld[s], srd[s], gcn_w, gcn_wb, gcn_b, smem, t);
        supp_row(g_support_g + s * DM, w1, b1, w2, b2, lg, lb, smem, t);
    }
    grid_bar(bbase, 1);

    // ---- Stage B: blocks 0-31: load + xproj(packed) + LSTM step0; blocks 32-47: SW(packed) ----
    int row0 = bid * 4;
    float cst = 0.0f;
    if (bid < 32) {
        {
            int r = t >> 7, k = t & 127;
            float v = g_query_g[(size_t)(row0 + r) * 128 + k];
            smem[SHT + k * 4 + r] = v;
            smem[SQ + r * 128 + k] = v;
            for (int i = t; i < FEW * 128; i += NT) smem[SSUP + i] = g_support_g[i];
        }
        __syncthreads();
        gemm4p<true>(smem, wih, bih, bhh, t);
        elt4p(smem, smem + SXP, cst, t, row0, 0, out);
    } else if (bid < 48) {
        int cb = bid - 32;   // 0..15, each does packed cols [cb*32, cb*32+32) for all 5 j
        if (t < 160) {
            int j = t >> 5;
            int cp = cb * 32 + (t & 31);
            int colo = (cp >> 7) * 256 + (cp & 127);
            float acc = 0.0f;
            #pragma unroll 16
            for (int k = 0; k < 128; k++)
                acc += g_support_g[j * 128 + k] * whh[(size_t)(128 + k) * 1024 + colo];
            g_SW[j * 512 + cp] = acc;
        }
    }
    grid_bar(bbase, 2);

    // ---- Stage C: LSTM steps 1..3, fully intra-block ----
    if (bid < 32) {
        #pragma unroll
        for (int s = 1; s < 4; s++) {
            gemm4p<false>(smem, whh, nullptr, nullptr, t);
            elt4p(smem, smem + SP1, cst, t, row0, (s == 3) ? 1 : 0, out);
        }
    }
}

// ---------------- host ----------------
extern "C" void kernel_launch(void* const* d_in, const int* in_sizes, int n_in,
                              void* d_out, int out_size) {
    const int2*  ql     = (const int2*)d_in[0];
    const int2*  qr     = (const int2*)d_in[1];
    const int2*  sl     = (const int2*)d_in[2];
    const int2*  sr     = (const int2*)d_in[3];
    const float* qld    = (const float*)d_in[4];
    const float* qrd    = (const float*)d_in[5];
    const float* sld    = (const float*)d_in[6];
    const float* srd    = (const float*)d_in[7];
    const float* ent    = (const float*)d_in[8];
    const float* relm   = (const float*)d_in[9];
    const float* gcn_w  = (const float*)d_in[10];
    const float* gcn_wb = (const float*)d_in[11];
    const float* gcn_b  = (const float*)d_in[12];
    const float* se_w1  = (const float*)d_in[13];
    const float* se_b1  = (const float*)d_in[14];
    const float* se_w2  = (const float*)d_in[15];
    const float* se_b2  = (const float*)d_in[16];
    const float* ln_g   = (const float*)d_in[17];
    const float* ln_b   = (const float*)d_in[18];
    const float* wih    = (const float*)d_in[19];
    const float* whh    = (const float*)d_in[20];
    const float* bih    = (const float*)d_in[21];
    const float* bhh    = (const float*)d_in[22];
    float* out = (float*)d_out;

    k1_scatter_rescal<<<GRID, NT>>>(ql, qr, sl, sr, ent, relm);
    k2_tail<<<GRID, NT>>>(qld, qrd, sld, srd, gcn_w, gcn_wb, gcn_b,
                          se_w1, se_b1, se_w2, se_b2, ln_g, ln_b,
                          wih, whh, bih, bhh, out);
}

// round 9
// speedup vs baseline: 2.3155x; 1.0995x over previous
#include <cuda_runtime.h>
#include <math.h>
#include <stdint.h>

#define Dd 64
#define DM 128
#define DI 256
#define Bq 128
#define NN 200
#define FEW 5
#define NRELS 500
#define NPQ (Bq*NN)
#define NPS (FEW*NN)
#define NPTOT (2*NPQ + 2*NPS)   // 53200
#define CAP 512
#define LN_EPS 0.001f
#define GRID 148
#define NT 512
#define TOTBAR (3ULL * GRID)    // k1: 1 barrier; k2: 2 barriers
#define SCHUNK 360
#define NROWS (Bq + FEW)        // 133
#define SUMSZ (NROWS * 128)     // 17024 floats

// k2 stage-A smem layout
#define AMS   0       // 128  g_sum row
#define AX    128     // 128  gcn output x
#define APART 256     // 512  k-split partials
#define ASA   768     // 256  relu activations
#define ASH   1024    // 128  pre-LN h
#define ASR   1152    // 64   reduce
#define ASC   1216    // 2

// k2 stage-B/C smem layout — packed 512-col gates
#define SXP   0       // 2048  xproj 4x512 (packed i|f|g|o)
#define SP1   2048    // 2048  partial kh=1 / final gates
#define SP2   4096    // 2048  partial kh=2
#define SP3   6144    // 2048  partial kh=3
#define SHT   8192    // 512   h transposed [128][4]
#define SQ    8704    // 512   query_g rows [4][128]
#define SSUP  9216    // 640   support_g [5][128]
#define SLOG  9856    // 32
#define SATT  9888    // 32
#define SRED  9920    // 80    16 warps x 5
#define SMEMF 10240

// ---------------- device scratch ----------------
__device__ int   g_cnt[512];                 // zero-init; self-zeroed each pass
__device__ int2  g_pairs[NRELS*CAP + 8];     // +8 pad for unconditional group loads
__device__ float g_sum[SUMSZ];               // per-row msg sums (zeroed each launch)
__device__ float g_query_g[Bq*DM];
__device__ float g_support_g[FEW*DM];
__device__ float g_SW[FEW*512];              // packed: support_g @ whh[128:]
__device__ int   g_relctr;
__device__ unsigned long long g_barcnt;      // monotonic, never reset

__device__ __forceinline__ float sigmoidf_(float x) { return 1.0f / (1.0f + expf(-x)); }

// packed fp32x2 helpers (Blackwell FFMA2)
#define FPACK2(d, f)      asm("mov.b64 %0, {%1, %1};" : "=l"(d) : "f"(f))
#define FMA2(acc, e, r)   asm("fma.rn.f32x2 %0, %1, %2, %3;" : "=l"(acc) : "l"(e), "l"(r), "l"(acc))
#define UNPACK2(lo, hi, v) asm("mov.b64 {%0, %1}, %2;" : "=f"(lo), "=f"(hi) : "l"(v))

__device__ __forceinline__ unsigned long long bar_read() {
    unsigned long long v;
    asm volatile("ld.global.acquire.gpu.u64 %0, [%1];" : "=l"(v) : "l"(&g_barcnt) : "memory");
    return v;
}
__device__ __forceinline__ void grid_bar(unsigned long long base, int k) {
    __syncthreads();
    if (threadIdx.x == 0) {
        __threadfence();
        atomicAdd(&g_barcnt, 1ULL);
        unsigned long long target = base + (unsigned long long)GRID * (unsigned long long)(k + 1);
        while (bar_read() < target) {}
        __threadfence();
    }
    __syncthreads();
}
__device__ __forceinline__ unsigned long long epoch_base() {
    return (bar_read() / TOTBAR) * TOTBAR;
}

// dest base in g_sum from original pair index
__device__ __forceinline__ int dest_base(int idx) {
    if (idx < 2*NPQ) {
        int half = (idx >= NPQ);
        int b = (idx - half * NPQ) / NN;
        return b * 128 + half * 64;
    } else {
        int i2 = idx - 2*NPQ;
        int half = (i2 >= NPS);
        int s = (i2 - half * NPS) / NN;
        return (Bq + s) * 128 + half * 64;
    }
}

// ================= KERNEL 1: scatter + binned RESCAL (REDG accumulate) =================
__global__ __launch_bounds__(NT, 1) void k1_scatter_rescal(
        const int2* __restrict__ ql, const int2* __restrict__ qr,
        const int2* __restrict__ sl, const int2* __restrict__ sr,
        const float* __restrict__ ent_emb, const float* __restrict__ rel_mat) {
    __shared__ __align__(16) float smem[8448];
    __shared__ unsigned long long s_base;
    __shared__ int s_r;
    int t = threadIdx.x, bid = blockIdx.x;
    if (t == 0) s_base = epoch_base();
    __syncthreads();
    unsigned long long bbase = s_base;

    // ---- zero g_sum + scatter; reset work queue ----
    if (bid == 0 && t == 0) g_relctr = 0;
    for (int i = bid * NT + t; i < SUMSZ; i += GRID * NT) g_sum[i] = 0.0f;
    {
        int lo = bid * SCHUNK, hi = min(lo + SCHUNK, NPTOT);
        for (int idx = lo + t; idx < hi; idx += NT) {
            int2 c;
            if (idx < NPQ)                 c = ql[idx];
            else if (idx < 2*NPQ)          c = qr[idx - NPQ];
            else if (idx < 2*NPQ + NPS)    c = sl[idx - 2*NPQ];
            else                           c = sr[idx - 2*NPQ - NPS];
            int pos = atomicAdd(&g_cnt[c.x], 1);
            if (pos < CAP) g_pairs[c.x * CAP + pos] = make_int2(idx, c.y);
        }
    }
    grid_bar(bbase, 0);

    // ---- binned RESCAL matvecs, dynamic rel queue, branch-free prefetch ----
    {
        float* sR   = smem;                  // 64*68 = 4352
        float* sE01 = smem + 4352;           // 16*128
        float* sE23 = smem + 6400;           // 16*128
        int w = t >> 5, lane = t & 31;
        for (;;) {
            if (t == 0) s_r = atomicAdd(&g_relctr, 1);
            __syncthreads();
            int r = s_r;
            if (r >= NRELS) break;
            int cnt = g_cnt[r];
            __syncthreads();
            if (t == 0) g_cnt[r] = 0;
            if (cnt > 0) {
                if (cnt > CAP) cnt = CAP;
                const float* R = rel_mat + (size_t)r * 4096;
                for (int i = t; i < 4096; i += NT) sR[(i >> 6) * 68 + (i & 63)] = R[i];
                __syncthreads();
                float* e01 = sE01 + w * 128;
                float* e23 = sE23 + w * 128;
                for (int base = w * 4; base < cnt; base += 64) {
                    int np = min(4, cnt - base);
                    int2 pr[4];
                    float2 ev[4];
                    #pragma unroll
                    for (int p = 0; p < 4; p++) pr[p] = g_pairs[r * CAP + base + p];
                    #pragma unroll
                    for (int p = 0; p < 4; p++)
                        ev[p] = ((const float2*)(ent_emb + (size_t)pr[p].y * 64))[lane];
                    #pragma unroll
                    for (int p = 0; p < 4; p++) {
                        float* dstE = (p < 2) ? e01 : e23;
                        int pp = p & 1;
                        dstE[4*lane + pp]     = ev[p].x;
                        dstE[4*lane + 2 + pp] = ev[p].y;
                    }
                    __syncwarp();
                    unsigned long long aA01=0, aA23=0, aB01=0, aB23=0;
                    #pragma unroll
                    for (int j4 = 0; j4 < 64; j4 += 4) {
                        float4 rA = *(const float4*)&sR[lane * 68 + j4];
                        float4 rB = *(const float4*)&sR[(lane + 32) * 68 + j4];
                        ulonglong2 E01a = *(const ulonglong2*)(e01 + j4*2);
                        ulonglong2 E01b = *(const ulonglong2*)(e01 + j4*2 + 4);
                        ulonglong2 E23a = *(const ulonglong2*)(e23 + j4*2);
                        ulonglong2 E23b = *(const ulonglong2*)(e23 + j4*2 + 4);
                        unsigned long long dA, dB;
                        FPACK2(dA, rA.x); FPACK2(dB, rB.x);
                        FMA2(aA01, E01a.x, dA); FMA2(aA23, E23a.x, dA);
                        FMA2(aB01, E01a.x, dB); FMA2(aB23, E23a.x, dB);
                        FPACK2(dA, rA.y); FPACK2(dB, rB.y);
                        FMA2(aA01, E01a.y, dA); FMA2(aA23, E23a.y, dA);
                        FMA2(aB01, E01a.y, dB); FMA2(aB23, E23a.y, dB);
                        FPACK2(dA, rA.z); FPACK2(dB, rB.z);
                        FMA2(aA01, E01b.x, dA); FMA2(aA23, E23b.x, dA);
                        FMA2(aB01, E01b.x, dB); FMA2(aB23, E23b.x, dB);
                        FPACK2(dA, rA.w); FPACK2(dB, rB.w);
                        FMA2(aA01, E01b.y, dA); FMA2(aA23, E23b.y, dA);
                        FMA2(aB01, E01b.y, dB); FMA2(aB23, E23b.y, dB);
                    }
                    float accA[4], accB[4];
                    UNPACK2(accA[0], accA[1], aA01); UNPACK2(accA[2], accA[3], aA23);
                    UNPACK2(accB[0], accB[1], aB01); UNPACK2(accB[2], accB[3], aB23);
                    #pragma unroll
                    for (int p = 0; p < 4; p++) {
                        if (p < np) {
                            int db = dest_base(pr[p].x);
                            atomicAdd(&g_sum[db + lane],      accA[p]);
                            atomicAdd(&g_sum[db + lane + 32], accB[p]);
                        }
                    }
                    __syncwarp();
                }
            }
            __syncthreads();
        }
    }
}

// ---------------- packed 4-row GEMM: (4x128) @ (128 x packed512), 4-way K-split ----------------
template<bool XPROJ>
__device__ __forceinline__ void gemm4p(float* sm, const float* __restrict__ Bmat,
        const float* __restrict__ bih, const float* __restrict__ bhh, int t) {
    int kh = t >> 7, u = t & 127;
    int c4p = u * 4;
    int gate = c4p >> 7;
    int colo = gate * 256 + (c4p & 127);
    const float* Bp = Bmat + (size_t)(kh * 32) * 1024 + colo;
    const float* Ap = sm + SHT + kh * 32 * 4;
    unsigned long long acc[8];
    #pragma unroll
    for (int i = 0; i < 8; i++) acc[i] = 0ULL;
    #pragma unroll 8
    for (int k = 0; k < 32; k++) {
        float4 a4 = *(const float4*)(Ap + k * 4);
        ulonglong2 bv = *(const ulonglong2*)(Bp + (size_t)k * 1024);
        unsigned long long ar;
        FPACK2(ar, a4.x); FMA2(acc[0], bv.x, ar); FMA2(acc[1], bv.y, ar);
        FPACK2(ar, a4.y); FMA2(acc[2], bv.x, ar); FMA2(acc[3], bv.y, ar);
        FPACK2(ar, a4.z); FMA2(acc[4], bv.x, ar); FMA2(acc[5], bv.y, ar);
        FPACK2(ar, a4.w); FMA2(acc[6], bv.x, ar); FMA2(acc[7], bv.y, ar);
    }
    if (kh) {
        float* pdst = sm + SP1 + (kh - 1) * 2048;
        #pragma unroll
        for (int r = 0; r < 4; r++) {
            float o0, o1, o2, o3;
            UNPACK2(o0, o1, acc[r*2]); UNPACK2(o2, o3, acc[r*2+1]);
            *(float4*)&pdst[r * 512 + c4p] = make_float4(o0, o1, o2, o3);
        }
    }
    __syncthreads();
    if (kh == 0) {
        float4 sw[FEW];
        float4 bb;
        if (XPROJ) {
            bb = make_float4(bih[colo]+bhh[colo], bih[colo+1]+bhh[colo+1],
                             bih[colo+2]+bhh[colo+2], bih[colo+3]+bhh[colo+3]);
        } else {
            #pragma unroll
            for (int j = 0; j < FEW; j++) sw[j] = *(const float4*)&g_SW[j * 512 + c4p];
        }
        #pragma unroll
        for (int r = 0; r < 4; r++) {
            float o0, o1, o2, o3;
            UNPACK2(o0, o1, acc[r*2]); UNPACK2(o2, o3, acc[r*2+1]);
            float4 p1 = *(const float4*)&sm[SP1 + r * 512 + c4p];
            float4 p2 = *(const float4*)&sm[SP2 + r * 512 + c4p];
            float4 p3 = *(const float4*)&sm[SP3 + r * 512 + c4p];
            o0 += p1.x + p2.x + p3.x; o1 += p1.y + p2.y + p3.y;
            o2 += p1.z + p2.z + p3.z; o3 += p1.w + p2.w + p3.w;
            if (XPROJ) {
                o0 += bb.x; o1 += bb.y; o2 += bb.z; o3 += bb.w;
                *(float4*)&sm[SXP + r * 512 + c4p] = make_float4(o0, o1, o2, o3);
            } else {
                float4 xv = *(const float4*)&sm[SXP + r * 512 + c4p];
                o0 += xv.x; o1 += xv.y; o2 += xv.z; o3 += xv.w;
                #pragma unroll
                for (int j = 0; j < FEW; j++) {
                    float aj = sm[SATT + r * 8 + j];
                    o0 += aj * sw[j].x; o1 += aj * sw[j].y;
                    o2 += aj * sw[j].z; o3 += aj * sw[j].w;
                }
                *(float4*)&sm[SP1 + r * 512 + c4p] = make_float4(o0, o1, o2, o3);
            }
        }
    }
    __syncthreads();
}

// ---------------- LSTM elementwise + attention, 2-sync version ----------------
__device__ __forceinline__ void elt4p(float* sm, const float* __restrict__ gp_base,
                                      float& c, int t, int row0, int last, float* __restrict__ out) {
    int r = t >> 7, u = t & 127;
    const float* gp = gp_base + r * 512;
    float gi = gp[u], gf = gp[128 + u], gg = gp[256 + u], go = gp[384 + u];
    c = sigmoidf_(gf) * c + sigmoidf_(gi) * tanhf(gg);
    float h = sm[SQ + r * 128 + u] + sigmoidf_(go) * tanhf(c);
    sm[SHT + u * 4 + r] = h;
    int lane = t & 31, wid = t >> 5;
    float p[FEW];
    #pragma unroll
    for (int j = 0; j < FEW; j++) p[j] = h * sm[SSUP + j * 128 + u];
    #pragma unroll
    for (int j = 0; j < FEW; j++)
        for (int o = 16; o; o >>= 1) p[j] += __shfl_down_sync(0xffffffff, p[j], o);
    if (lane == 0) {
        #pragma unroll
        for (int j = 0; j < FEW; j++) sm[SRED + wid * 5 + j] = p[j];
    }
    __syncthreads();
    if (t < 32) {
        int rr = t >> 3, j = t & 7;
        if (j < FEW) {
            int w0 = rr * 4;
            sm[SLOG + rr * 8 + j] = sm[SRED + w0*5 + j] + sm[SRED + (w0+1)*5 + j]
                                  + sm[SRED + (w0+2)*5 + j] + sm[SRED + (w0+3)*5 + j];
        }
    }
    __syncthreads();
    if (last) {
        if (t < 4) {
            #pragma unroll
            for (int j = 0; j < FEW; j++) out[(row0 + t) * FEW + j] = sm[SLOG + t * 8 + j];
        }
        return;
    }
    if (t < 4) {
        float mx = sm[SLOG + t * 8];
        #pragma unroll
        for (int j = 1; j < FEW; j++) mx = fmaxf(mx, sm[SLOG + t * 8 + j]);
        float s = 0.0f, e[FEW];
        #pragma unroll
        for (int j = 0; j < FEW; j++) { e[j] = expf(sm[SLOG + t * 8 + j] - mx); s += e[j]; }
        #pragma unroll
        for (int j = 0; j < FEW; j++) sm[SATT + t * 8 + j] = e[j] / s;
    }
    __syncthreads();
}

// ================= KERNEL 2: gcn+supp (k-split GEMVs) + LSTM tail =================
__global__ __launch_bounds__(NT, 1) void k2_tail(
        const float* __restrict__ qld, const float* __restrict__ qrd,
        const float* __restrict__ sld, const float* __restrict__ srd,
        const float* __restrict__ gcn_w, const float* __restrict__ gcn_wb, const float* __restrict__ gcn_b,
        const float* __restrict__ w1, const float* __restrict__ b1,
        const float* __restrict__ w2, const float* __restrict__ b2,
        const float* __restrict__ lg, const float* __restrict__ lb,
        const float* __restrict__ wih, const float* __restrict__ whh,
        const float* __restrict__ bih, const float* __restrict__ bhh,
        float* __restrict__ out) {
    __shared__ __align__(16) float smem[SMEMF];
    __shared__ unsigned long long s_base;
    int t = threadIdx.x, bid = blockIdx.x;
    if (t == 0) s_base = epoch_base();
    __syncthreads();
    unsigned long long bbase = s_base;

    // ---- Stage A: gcn matvec + support encoder, k-split across all 512 threads ----
    if (bid < NROWS) {
        if (t < 128) smem[AMS + t] = g_sum[bid * 128 + t];
        __syncthreads();
        {   // gcn matvec: 128 outputs x 4-way k-split
            int o = t & 127, ks = t >> 7;
            int hh = o >> 6, col = o & 63;
            float acc = 0.0f;
            #pragma unroll
            for (int i = 0; i < 16; i++) {
                int k = ks * 16 + i;
                acc += smem[AMS + hh * 64 + k] * gcn_w[k * 64 + col];
            }
            smem[APART + ks * 128 + o] = acc;
        }
        __syncthreads();
        float degL = (bid < Bq) ? qld[bid] : sld[bid - Bq];
        float degR = (bid < Bq) ? qrd[bid] : srd[bid - Bq];
        if (t < 128) {
            float acc = smem[APART + t] + smem[APART + 128 + t]
                      + smem[APART + 256 + t] + smem[APART + 384 + t];
            acc += (float)NN * (gcn_wb[t & 63] + gcn_b[t & 63]);
            smem[AX + t] = tanhf(acc / ((t >> 6) ? degR : degL));
        }
        __syncthreads();
        {   // GEMV1: 256 outputs x 2-way k-split (K=128)
            int half = t >> 8, o = t & 255;
            float acc = 0.0f;
            #pragma unroll
            for (int i = 0; i < 64; i++) {
                int k = half * 64 + i;
                acc += smem[AX + k] * w1[k * DI + o];
            }
            smem[APART + half * 256 + o] = acc;
        }
        __syncthreads();
        if (t < DI) smem[ASA + t] = fmaxf(smem[APART + t] + smem[APART + 256 + t] + b1[t], 0.0f);
        __syncthreads();
        {   // GEMV2: 128 outputs x 4-way k-split (K=256)
            int ks = t >> 7, o = t & 127;
            float acc = 0.0f;
            #pragma unroll
            for (int i = 0; i < 64; i++) {
                int k = ks * 64 + i;
                acc += smem[ASA + k] * w2[k * DM + o];
            }
            smem[APART + ks * 128 + o] = acc;
        }
        __syncthreads();
        if (t < DM) {
            smem[ASH + t] = smem[APART + t] + smem[APART + 128 + t] + smem[APART + 256 + t]
                          + smem[APART + 384 + t] + b2[t] + smem[AX + t];
        }
        __syncthreads();
        // LayerNorm (ddof=1)
        if (t < 64) smem[ASR + t] = smem[ASH + t] + smem[ASH + t + 64];
        __syncthreads();
        if (t < 32) {
            float v = smem[ASR + t] + smem[ASR + t + 32];
            for (int o = 16; o; o >>= 1) v += __shfl_down_sync(0xffffffff, v, o);
            if (t == 0) smem[ASC] = v / (float)DM;
        }
        __syncthreads();
        float mu = smem[ASC];
        if (t < 64) {
            float d0 = smem[ASH + t] - mu, d1 = smem[ASH + t + 64] - mu;
            smem[ASR + t] = d0 * d0 + d1 * d1;
        }
        __syncthreads();
        if (t < 32) {
            float v = smem[ASR + t] + smem[ASR + t + 32];
            for (int o = 16; o; o >>= 1) v += __shfl_down_sync(0xffffffff, v, o);
            if (t == 0) smem[ASC + 1] = sqrtf(v / (float)(DM - 1));
        }
        __syncthreads();
        if (t < DM) {
            float* y = (bid < Bq) ? (g_query_g + bid * DM) : (g_support_g + (bid - Bq) * DM);
            y[t] = (smem[ASH + t] - mu) / (smem[ASC + 1] + LN_EPS) * lg[t] + lb[t];
        }
    }
    grid_bar(bbase, 1);

    // ---- Stage B: blocks 0-31: xproj + step0; blocks 32-47: SW(packed) ----
    int row0 = bid * 4;
    float cst = 0.0f;
    if (bid < 32) {
        {
            int r = t >> 7, k = t & 127;
            float v = g_query_g[(size_t)(row0 + r) * 128 + k];
            smem[SHT + k * 4 + r] = v;
            smem[SQ + r * 128 + k] = v;
            for (int i = t; i < FEW * 128; i += NT) smem[SSUP + i] = g_support_g[i];
        }
        __syncthreads();
        gemm4p<true>(smem, wih, bih, bhh, t);
        elt4p(smem, smem + SXP, cst, t, row0, 0, out);
    } else if (bid < 48) {
        int cb = bid - 32;
        if (t < 160) {
            int j = t >> 5;
            int cp = cb * 32 + (t & 31);
            int colo = (cp >> 7) * 256 + (cp & 127);
            float acc = 0.0f;
            #pragma unroll 16
            for (int k = 0; k < 128; k++)
                acc += g_support_g[j * 128 + k] * whh[(size_t)(128 + k) * 1024 + colo];
            g_SW[j * 512 + cp] = acc;
        }
    }
    grid_bar(bbase, 2);

    // ---- Stage C: LSTM steps 1..3, fully intra-block ----
    if (bid < 32) {
        #pragma unroll
        for (int s = 1; s < 4; s++) {
            gemm4p<false>(smem, whh, nullptr, nullptr, t);
            elt4p(smem, smem + SP1, cst, t, row0, (s == 3) ? 1 : 0, out);
        }
    }
}

// ---------------- host ----------------
extern "C" void kernel_launch(void* const* d_in, const int* in_sizes, int n_in,
                              void* d_out, int out_size) {
    const int2*  ql     = (const int2*)d_in[0];
    const int2*  qr     = (const int2*)d_in[1];
    const int2*  sl     = (const int2*)d_in[2];
    const int2*  sr     = (const int2*)d_in[3];
    const float* qld    = (const float*)d_in[4];
    const float* qrd    = (const float*)d_in[5];
    const float* sld    = (const float*)d_in[6];
    const float* srd    = (const float*)d_in[7];
    const float* ent    = (const float*)d_in[8];
    const float* relm   = (const float*)d_in[9];
    const float* gcn_w  = (const float*)d_in[10];
    const float* gcn_wb = (const float*)d_in[11];
    const float* gcn_b  = (const float*)d_in[12];
    const float* se_w1  = (const float*)d_in[13];
    const float* se_b1  = (const float*)d_in[14];
    const float* se_w2  = (const float*)d_in[15];
    const float* se_b2  = (const float*)d_in[16];
    const float* ln_g   = (const float*)d_in[17];
    const float* ln_b   = (const float*)d_in[18];
    const float* wih    = (const float*)d_in[19];
    const float* whh    = (const float*)d_in[20];
    const float* bih    = (const float*)d_in[21];
    const float* bhh    = (const float*)d_in[22];
    float* out = (float*)d_out;

    k1_scatter_rescal<<<GRID, NT>>>(ql, qr, sl, sr, ent, relm);
    k2_tail<<<GRID, NT>>>(qld, qrd, sld, srd, gcn_w, gcn_wb, gcn_b,
                          se_w1, se_b1, se_w2, se_b2, ln_g, ln_b,
                          wih, whh, bih, bhh, out);
}